// round 7
// baseline (speedup 1.0000x reference)
#include <cuda_runtime.h>
#include <math.h>

#define BATCH   4
#define SEQ     4096
#define DMODEL  1024
#define DINNER  2048
#define DSTATE  16
#define DTRANK  64
#define NTOK    (BATCH * SEQ)          // 16384
#define DBL_W   (DTRANK + 2 * DSTATE)  // 96

// ---------------- scratch (static device globals: allocation-free) ----------
__device__ float g_u  [(size_t)NTOK * DMODEL];        //  64 MB normalized x
__device__ float g_xz [(size_t)NTOK * 2 * DINNER];    // 256 MB in_proj out (xc | z)
__device__ float g_xc [(size_t)NTOK * DINNER];        // 128 MB conv+silu out
__device__ float g_dbl[(size_t)NTOK * DBL_W];         //   6 MB x_proj out (dt_low|B|C)
__device__ float g_dt [(size_t)NTOK * DINNER];        // 128 MB softplus(dt_proj)
__device__ float g_y  [(size_t)NTOK * DINNER];        // 128 MB gated scan out

// ---------------- RMSNorm: one block per token ------------------------------
__global__ __launch_bounds__(256) void rmsnorm_kernel(
    const float* __restrict__ x, float* __restrict__ u)
{
    size_t row = blockIdx.x;
    const float4* xr = reinterpret_cast<const float4*>(x + row * DMODEL);
    float4*       ur = reinterpret_cast<float4*>(u + row * DMODEL);
    int tid = threadIdx.x;                 // 256 threads * 4 = 1024
    float4 v = xr[tid];
    float ss = v.x * v.x + v.y * v.y + v.z * v.z + v.w * v.w;
    #pragma unroll
    for (int o = 16; o > 0; o >>= 1) ss += __shfl_xor_sync(0xffffffffu, ss, o);
    __shared__ float ws[8];
    if ((tid & 31) == 0) ws[tid >> 5] = ss;
    __syncthreads();
    float tot = 0.f;
    #pragma unroll
    for (int w = 0; w < 8; w++) tot += ws[w];
    float sc = rsqrtf(tot * (1.f / DMODEL) + 1e-6f);
    ur[tid] = make_float4(v.x * sc, v.y * sc, v.z * sc, v.w * sc);
}

// ---------------- generic tiled SGEMM: C[M,N] = A[M,K] @ W[N,K]^T -----------
// EPI: 0 = none, 1 = softplus(acc + bias[n]), 2 = acc + resid[row*ldc+col]
template <int EPI>
__global__ __launch_bounds__(256) void sgemm_kernel(
    const float* __restrict__ A, int lda,
    const float* __restrict__ W, int ldb,
    float* __restrict__ C, int ldc,
    int N, int K,
    const float* __restrict__ bias,
    const float* __restrict__ resid)
{
    constexpr int BM = 64, BN = 64, BK = 16;
    __shared__ __align__(16) float As[BK][BM + 4];
    __shared__ __align__(16) float Bs[BK][BN + 4];

    int tid  = threadIdx.x;
    int brow = blockIdx.y * BM;
    int bcol = blockIdx.x * BN;
    int lr = tid >> 2;           // 0..63 : tile row (A) / tile n (W)
    int lk = (tid & 3) * 4;      // 0,4,8,12 : k sub-offset
    int tm = (tid >> 4) << 2;    // 0..60 microtile row
    int tn = (tid & 15) << 2;    // 0..60 microtile col

    float acc[4][4];
    #pragma unroll
    for (int i = 0; i < 4; i++)
        #pragma unroll
        for (int j = 0; j < 4; j++) acc[i][j] = 0.f;

    for (int k0 = 0; k0 < K; k0 += BK) {
        float4 av = *reinterpret_cast<const float4*>(
            &A[(size_t)(brow + lr) * lda + k0 + lk]);
        As[lk + 0][lr] = av.x; As[lk + 1][lr] = av.y;
        As[lk + 2][lr] = av.z; As[lk + 3][lr] = av.w;

        int bn = bcol + lr;
        float4 bv = make_float4(0.f, 0.f, 0.f, 0.f);
        if (bn < N)
            bv = *reinterpret_cast<const float4*>(&W[(size_t)bn * ldb + k0 + lk]);
        Bs[lk + 0][lr] = bv.x; Bs[lk + 1][lr] = bv.y;
        Bs[lk + 2][lr] = bv.z; Bs[lk + 3][lr] = bv.w;

        __syncthreads();
        #pragma unroll
        for (int kk = 0; kk < BK; kk++) {
            float4 a = *reinterpret_cast<const float4*>(&As[kk][tm]);
            float4 b = *reinterpret_cast<const float4*>(&Bs[kk][tn]);
            float ar[4] = {a.x, a.y, a.z, a.w};
            float br[4] = {b.x, b.y, b.z, b.w};
            #pragma unroll
            for (int i = 0; i < 4; i++)
                #pragma unroll
                for (int j = 0; j < 4; j++)
                    acc[i][j] = fmaf(ar[i], br[j], acc[i][j]);
        }
        __syncthreads();
    }

    #pragma unroll
    for (int i = 0; i < 4; i++) {
        int row = brow + tm + i;
        #pragma unroll
        for (int j = 0; j < 4; j++) {
            int col = bcol + tn + j;
            if (col < N) {
                float v = acc[i][j];
                if (EPI == 1) {
                    v += bias[col];
                    v = (v > 20.f) ? v : log1pf(expf(v));
                } else if (EPI == 2) {
                    v += resid[(size_t)row * ldc + col];
                }
                C[(size_t)row * ldc + col] = v;
            }
        }
    }
}

// ---------------- causal depthwise conv (width 4) + SiLU --------------------
__global__ __launch_bounds__(256) void conv_silu_kernel(
    const float* __restrict__ xz,      // [NTOK, 4096], xc branch = cols [0,2048)
    const float* __restrict__ cw,      // [2048, 4]
    const float* __restrict__ cb,      // [2048]
    float* __restrict__ xc)            // [NTOK, 2048]
{
    int idx = blockIdx.x * blockDim.x + threadIdx.x;   // over NTOK*DINNER
    int e = idx & (DINNER - 1);
    int r = idx >> 11;            // token row = b*SEQ + t
    int t = r & (SEQ - 1);
    float4 w = *reinterpret_cast<const float4*>(cw + (size_t)e * 4);
    float wv[4] = {w.x, w.y, w.z, w.w};
    float acc = cb[e];
    #pragma unroll
    for (int k = 0; k < 4; k++) {
        int tt = t - 3 + k;
        if (tt >= 0)
            acc = fmaf(wv[k], xz[(size_t)(r - 3 + k) * (2 * DINNER) + e], acc);
    }
    xc[idx] = acc / (1.f + __expf(-acc));
}

// ---------------- selective scan + D skip + SiLU(z) gate --------------------
// one thread per (batch, channel); 16 states in registers; B/C loads are
// lane-uniform (broadcast) float4s.
__global__ void scan_kernel(
    const float* __restrict__ dt,     // [NTOK, DINNER] softplus'd
    const float* __restrict__ xc,     // [NTOK, DINNER]
    const float* __restrict__ dbl,    // [NTOK, 96]; B = cols 64..79, C = 80..95
    const float* __restrict__ xz,     // z = cols [2048,4096)
    const float* __restrict__ A_log,  // [DINNER, 16]
    const float* __restrict__ D_skip, // [DINNER]
    float* __restrict__ y)            // [NTOK, DINNER]
{
    int ch = blockIdx.x * 32 + threadIdx.x;   // 0..8191
    int b = ch >> 11;
    int e = ch & (DINNER - 1);

    float A[DSTATE], h[DSTATE];
    #pragma unroll
    for (int s = 0; s < DSTATE; s++) {
        A[s] = -expf(A_log[(size_t)e * DSTATE + s]);
        h[s] = 0.f;
    }
    float Dv = D_skip[e];
    size_t base = (size_t)b * SEQ;

    for (int t = 0; t < SEQ; t++) {
        size_t r = base + t;
        float dtv = dt[r * DINNER + e];
        float xv  = xc[r * DINNER + e];
        const float4* p = reinterpret_cast<const float4*>(dbl + r * DBL_W + DTRANK);
        float4 B0 = p[0], B1 = p[1], B2 = p[2], B3 = p[3];
        float4 C0 = p[4], C1 = p[5], C2 = p[6], C3 = p[7];
        float Bv[16] = {B0.x,B0.y,B0.z,B0.w, B1.x,B1.y,B1.z,B1.w,
                        B2.x,B2.y,B2.z,B2.w, B3.x,B3.y,B3.z,B3.w};
        float Cv[16] = {C0.x,C0.y,C0.z,C0.w, C1.x,C1.y,C1.z,C1.w,
                        C2.x,C2.y,C2.z,C2.w, C3.x,C3.y,C3.z,C3.w};
        float dtx = dtv * xv;
        float yv = 0.f;
        #pragma unroll
        for (int s = 0; s < DSTATE; s++) {
            h[s] = fmaf(h[s], __expf(dtv * A[s]), dtx * Bv[s]);
            yv = fmaf(h[s], Cv[s], yv);
        }
        float zv = xz[r * (2 * DINNER) + DINNER + e];
        float g = zv / (1.f + __expf(-zv));
        y[r * DINNER + e] = (yv + Dv * xv) * g;
    }
}

// ---------------- launch ----------------------------------------------------
extern "C" void kernel_launch(void* const* d_in, const int* in_sizes, int n_in,
                              void* d_out, int out_size)
{
    const float* x         = (const float*)d_in[0];
    const float* in_proj_w = (const float*)d_in[1];
    const float* conv_w    = (const float*)d_in[2];
    const float* conv_b    = (const float*)d_in[3];
    const float* x_proj_w  = (const float*)d_in[4];
    const float* dt_proj_w = (const float*)d_in[5];
    const float* dt_proj_b = (const float*)d_in[6];
    const float* A_log     = (const float*)d_in[7];
    const float* D_skip    = (const float*)d_in[8];
    const float* out_proj_w= (const float*)d_in[9];
    float* out = (float*)d_out;

    float *u, *xz, *xc, *dbl, *dtb, *yb;
    cudaGetSymbolAddress((void**)&u,   g_u);
    cudaGetSymbolAddress((void**)&xz,  g_xz);
    cudaGetSymbolAddress((void**)&xc,  g_xc);
    cudaGetSymbolAddress((void**)&dbl, g_dbl);
    cudaGetSymbolAddress((void**)&dtb, g_dt);
    cudaGetSymbolAddress((void**)&yb,  g_y);

    // 1) RMSNorm
    rmsnorm_kernel<<<NTOK, 256>>>(x, u);

    // 2) in_proj: [16384,1024] @ [4096,1024]^T -> [16384,4096]
    sgemm_kernel<0><<<dim3((2 * DINNER) / 64, NTOK / 64), 256>>>(
        u, DMODEL, in_proj_w, DMODEL, xz, 2 * DINNER,
        2 * DINNER, DMODEL, nullptr, nullptr);

    // 3) causal depthwise conv + SiLU -> xc
    conv_silu_kernel<<<(NTOK * DINNER) / 256, 256>>>(xz, conv_w, conv_b, xc);

    // 4) x_proj: [16384,2048] @ [96,2048]^T -> [16384,96]
    sgemm_kernel<0><<<dim3(2, NTOK / 64), 256>>>(
        xc, DINNER, x_proj_w, DINNER, dbl, DBL_W,
        DBL_W, DINNER, nullptr, nullptr);

    // 5) dt_proj + bias + softplus: [16384,64] @ [2048,64]^T -> [16384,2048]
    sgemm_kernel<1><<<dim3(DINNER / 64, NTOK / 64), 256>>>(
        dbl, DBL_W, dt_proj_w, DTRANK, dtb, DINNER,
        DINNER, DTRANK, dt_proj_b, nullptr);

    // 6) selective scan + D skip + SiLU(z) gating -> y
    scan_kernel<<<(BATCH * DINNER) / 32, 32>>>(dtb, xc, dbl, xz, A_log, D_skip, yb);

    // 7) out_proj + residual: [16384,2048] @ [1024,2048]^T + x -> out
    sgemm_kernel<2><<<dim3(DMODEL / 64, NTOK / 64), 256>>>(
        yb, DINNER, out_proj_w, DINNER, out, DMODEL,
        DMODEL, DINNER, nullptr, x);
}

// round 9
// speedup vs baseline: 1.6495x; 1.6495x over previous
#include <cuda_runtime.h>
#include <math.h>
#include <stdint.h>

#define BATCH   4
#define SEQ     4096
#define DMODEL  1024
#define DINNER  2048
#define DSTATE  16
#define DTRANK  64
#define NTOK    (BATCH * SEQ)          // 16384
#define DBL_W   (DTRANK + 2 * DSTATE)  // 96

// ---------------- scratch (static device globals: allocation-free) ----------
__device__ float g_u  [(size_t)NTOK * DMODEL];
__device__ float g_xz [(size_t)NTOK * 2 * DINNER];
__device__ float g_xc [(size_t)NTOK * DINNER];
__device__ float g_dbl[(size_t)NTOK * DBL_W];
__device__ float g_dt [(size_t)NTOK * DINNER];
__device__ float g_y  [(size_t)NTOK * DINNER];

// =================== tf32 mma.sync GEMM: C = A[M,K] @ W[N,K]^T ==============
// 128x128 CTA tile, BK=16, 256 threads (8 warps as 2x4), warp tile 64x32
// (4x4 grid of m16n8k8). SMEM layout [row][k] with stride 20 words:
// fragment reads provably conflict-free. Double buffered, 1 sync per chunk.
// EPI: 0 none, 1 softplus(acc+bias[n]), 2 acc+resid.

__device__ __forceinline__ uint32_t f2tf32(float f) {
    uint32_t o;
    asm("cvt.rn.tf32.f32 %0, %1;" : "=r"(o) : "f"(f));
    return o;
}
__device__ __forceinline__ void mma_tf32(float* d, const uint32_t* a,
                                         const uint32_t* b) {
    asm volatile(
        "mma.sync.aligned.m16n8k8.row.col.f32.tf32.tf32.f32 "
        "{%0,%1,%2,%3}, {%4,%5,%6,%7}, {%8,%9}, {%0,%1,%2,%3};"
        : "+f"(d[0]), "+f"(d[1]), "+f"(d[2]), "+f"(d[3])
        : "r"(a[0]), "r"(a[1]), "r"(a[2]), "r"(a[3]), "r"(b[0]), "r"(b[1]));
}

#define SSTRIDE 20   // words per 16-float k-row (pad 4): conflict-free frag reads

template <int EPI>
__global__ __launch_bounds__(256) void mma_gemm_kernel(
    const float* __restrict__ A, int lda,
    const float* __restrict__ W, int ldb,
    float* __restrict__ C, int ldc,
    int N, int K,
    const float* __restrict__ bias,
    const float* __restrict__ resid)
{
    __shared__ uint32_t As[2][128 * SSTRIDE];
    __shared__ uint32_t Bs[2][128 * SSTRIDE];

    int tid = threadIdx.x;
    int lane = tid & 31;
    int q = lane >> 2, c = lane & 3;
    int wid = tid >> 5;
    int wm = wid >> 2, wn = wid & 3;             // 2 x 4 warp grid
    int brow = blockIdx.y * 128, bcol = blockIdx.x * 128;

    // global->smem mapping: 512 float4 per array per chunk, 2 per thread
    int r0 = tid >> 2, r1 = r0 + 64;
    int kq = (tid & 3) * 4;
    int nrow0 = bcol + r0, nrow1 = bcol + r1;
    bool bv0 = nrow0 < N, bv1 = nrow1 < N;

    const float4 f4z = make_float4(0.f, 0.f, 0.f, 0.f);

    float acc[4][4][4];
    #pragma unroll
    for (int mt = 0; mt < 4; mt++)
        #pragma unroll
        for (int nt = 0; nt < 4; nt++)
            #pragma unroll
            for (int i = 0; i < 4; i++) acc[mt][nt][i] = 0.f;

    // ---- initial chunk -> buffer 0 ----
    {
        float4 a0 = *reinterpret_cast<const float4*>(&A[(size_t)(brow + r0) * lda + kq]);
        float4 a1 = *reinterpret_cast<const float4*>(&A[(size_t)(brow + r1) * lda + kq]);
        float4 b0 = bv0 ? *reinterpret_cast<const float4*>(&W[(size_t)nrow0 * ldb + kq]) : f4z;
        float4 b1 = bv1 ? *reinterpret_cast<const float4*>(&W[(size_t)nrow1 * ldb + kq]) : f4z;
        uint4 u;
        u.x = f2tf32(a0.x); u.y = f2tf32(a0.y); u.z = f2tf32(a0.z); u.w = f2tf32(a0.w);
        *reinterpret_cast<uint4*>(&As[0][r0 * SSTRIDE + kq]) = u;
        u.x = f2tf32(a1.x); u.y = f2tf32(a1.y); u.z = f2tf32(a1.z); u.w = f2tf32(a1.w);
        *reinterpret_cast<uint4*>(&As[0][r1 * SSTRIDE + kq]) = u;
        u.x = f2tf32(b0.x); u.y = f2tf32(b0.y); u.z = f2tf32(b0.z); u.w = f2tf32(b0.w);
        *reinterpret_cast<uint4*>(&Bs[0][r0 * SSTRIDE + kq]) = u;
        u.x = f2tf32(b1.x); u.y = f2tf32(b1.y); u.z = f2tf32(b1.z); u.w = f2tf32(b1.w);
        *reinterpret_cast<uint4*>(&Bs[0][r1 * SSTRIDE + kq]) = u;
    }
    __syncthreads();

    int nch = K >> 4;
    for (int ch = 0; ch < nch; ch++) {
        int s = ch & 1;
        // prefetch next chunk
        float4 pa0, pa1, pb0, pb1;
        bool more = (ch + 1 < nch);
        if (more) {
            int k0 = (ch + 1) << 4;
            pa0 = *reinterpret_cast<const float4*>(&A[(size_t)(brow + r0) * lda + k0 + kq]);
            pa1 = *reinterpret_cast<const float4*>(&A[(size_t)(brow + r1) * lda + k0 + kq]);
            pb0 = bv0 ? *reinterpret_cast<const float4*>(&W[(size_t)nrow0 * ldb + k0 + kq]) : f4z;
            pb1 = bv1 ? *reinterpret_cast<const float4*>(&W[(size_t)nrow1 * ldb + k0 + kq]) : f4z;
        }
        // compute: 2 k-steps of 8
        #pragma unroll
        for (int ks = 0; ks < 2; ks++) {
            int kb = ks * 8 + c;
            uint32_t af[4][4];
            #pragma unroll
            for (int mt = 0; mt < 4; mt++) {
                int m = wm * 64 + mt * 16 + q;
                af[mt][0] = As[s][m * SSTRIDE + kb];
                af[mt][1] = As[s][(m + 8) * SSTRIDE + kb];
                af[mt][2] = As[s][m * SSTRIDE + kb + 4];
                af[mt][3] = As[s][(m + 8) * SSTRIDE + kb + 4];
            }
            uint32_t bf[4][2];
            #pragma unroll
            for (int nt = 0; nt < 4; nt++) {
                int n = wn * 32 + nt * 8 + q;
                bf[nt][0] = Bs[s][n * SSTRIDE + kb];
                bf[nt][1] = Bs[s][n * SSTRIDE + kb + 4];
            }
            #pragma unroll
            for (int mt = 0; mt < 4; mt++)
                #pragma unroll
                for (int nt = 0; nt < 4; nt++)
                    mma_tf32(acc[mt][nt], af[mt], bf[nt]);
        }
        if (more) {
            int d = s ^ 1;
            uint4 u;
            u.x = f2tf32(pa0.x); u.y = f2tf32(pa0.y); u.z = f2tf32(pa0.z); u.w = f2tf32(pa0.w);
            *reinterpret_cast<uint4*>(&As[d][r0 * SSTRIDE + kq]) = u;
            u.x = f2tf32(pa1.x); u.y = f2tf32(pa1.y); u.z = f2tf32(pa1.z); u.w = f2tf32(pa1.w);
            *reinterpret_cast<uint4*>(&As[d][r1 * SSTRIDE + kq]) = u;
            u.x = f2tf32(pb0.x); u.y = f2tf32(pb0.y); u.z = f2tf32(pb0.z); u.w = f2tf32(pb0.w);
            *reinterpret_cast<uint4*>(&Bs[d][r0 * SSTRIDE + kq]) = u;
            u.x = f2tf32(pb1.x); u.y = f2tf32(pb1.y); u.z = f2tf32(pb1.z); u.w = f2tf32(pb1.w);
            *reinterpret_cast<uint4*>(&Bs[d][r1 * SSTRIDE + kq]) = u;
            __syncthreads();
        }
    }

    // ---- epilogue: registers -> global as float2 pairs ----
    #pragma unroll
    for (int mt = 0; mt < 4; mt++) {
        #pragma unroll
        for (int nt = 0; nt < 4; nt++) {
            int gr = brow + wm * 64 + mt * 16 + q;
            int gc = bcol + wn * 32 + nt * 8 + c * 2;
            if (gc < N) {
                #pragma unroll
                for (int half = 0; half < 2; half++) {
                    int row = gr + half * 8;
                    float v0 = acc[mt][nt][half * 2 + 0];
                    float v1 = acc[mt][nt][half * 2 + 1];
                    if (EPI == 1) {
                        v0 += bias[gc];     v1 += bias[gc + 1];
                        v0 = (v0 > 20.f) ? v0 : log1pf(expf(v0));
                        v1 = (v1 > 20.f) ? v1 : log1pf(expf(v1));
                    } else if (EPI == 2) {
                        float2 rz = *reinterpret_cast<const float2*>(
                            &resid[(size_t)row * ldc + gc]);
                        v0 += rz.x; v1 += rz.y;
                    }
                    float2 o; o.x = v0; o.y = v1;
                    *reinterpret_cast<float2*>(&C[(size_t)row * ldc + gc]) = o;
                }
            }
        }
    }
}

// ---------------- RMSNorm: one block per token ------------------------------
__global__ __launch_bounds__(256) void rmsnorm_kernel(
    const float* __restrict__ x, float* __restrict__ u)
{
    size_t row = blockIdx.x;
    const float4* xr = reinterpret_cast<const float4*>(x + row * DMODEL);
    float4*       ur = reinterpret_cast<float4*>(u + row * DMODEL);
    int tid = threadIdx.x;
    float4 v = xr[tid];
    float ss = v.x * v.x + v.y * v.y + v.z * v.z + v.w * v.w;
    #pragma unroll
    for (int o = 16; o > 0; o >>= 1) ss += __shfl_xor_sync(0xffffffffu, ss, o);
    __shared__ float ws[8];
    if ((tid & 31) == 0) ws[tid >> 5] = ss;
    __syncthreads();
    float tot = 0.f;
    #pragma unroll
    for (int w = 0; w < 8; w++) tot += ws[w];
    float sc = rsqrtf(tot * (1.f / DMODEL) + 1e-6f);
    ur[tid] = make_float4(v.x * sc, v.y * sc, v.z * sc, v.w * sc);
}

// ---------------- causal depthwise conv (width 4) + SiLU --------------------
__global__ __launch_bounds__(256) void conv_silu_kernel(
    const float* __restrict__ xz,
    const float* __restrict__ cw,
    const float* __restrict__ cb,
    float* __restrict__ xc)
{
    int idx = blockIdx.x * blockDim.x + threadIdx.x;
    int e = idx & (DINNER - 1);
    int r = idx >> 11;
    int t = r & (SEQ - 1);
    float4 w = *reinterpret_cast<const float4*>(cw + (size_t)e * 4);
    float wv[4] = {w.x, w.y, w.z, w.w};
    float acc = cb[e];
    #pragma unroll
    for (int k = 0; k < 4; k++) {
        int tt = t - 3 + k;
        if (tt >= 0)
            acc = fmaf(wv[k], xz[(size_t)(r - 3 + k) * (2 * DINNER) + e], acc);
    }
    xc[idx] = acc / (1.f + __expf(-acc));
}

// ---------------- selective scan + D skip + SiLU(z) gate --------------------
__global__ void scan_kernel(
    const float* __restrict__ dt,
    const float* __restrict__ xc,
    const float* __restrict__ dbl,
    const float* __restrict__ xz,
    const float* __restrict__ A_log,
    const float* __restrict__ D_skip,
    float* __restrict__ y)
{
    int ch = blockIdx.x * 32 + threadIdx.x;
    int b = ch >> 11;
    int e = ch & (DINNER - 1);

    float A[DSTATE], h[DSTATE];
    #pragma unroll
    for (int s = 0; s < DSTATE; s++) {
        A[s] = -expf(A_log[(size_t)e * DSTATE + s]);
        h[s] = 0.f;
    }
    float Dv = D_skip[e];
    size_t base = (size_t)b * SEQ;

    for (int t = 0; t < SEQ; t++) {
        size_t r = base + t;
        float dtv = dt[r * DINNER + e];
        float xv  = xc[r * DINNER + e];
        const float4* p = reinterpret_cast<const float4*>(dbl + r * DBL_W + DTRANK);
        float4 B0 = p[0], B1 = p[1], B2 = p[2], B3 = p[3];
        float4 C0 = p[4], C1 = p[5], C2 = p[6], C3 = p[7];
        float Bv[16] = {B0.x,B0.y,B0.z,B0.w, B1.x,B1.y,B1.z,B1.w,
                        B2.x,B2.y,B2.z,B2.w, B3.x,B3.y,B3.z,B3.w};
        float Cv[16] = {C0.x,C0.y,C0.z,C0.w, C1.x,C1.y,C1.z,C1.w,
                        C2.x,C2.y,C2.z,C2.w, C3.x,C3.y,C3.z,C3.w};
        float dtx = dtv * xv;
        float yv = 0.f;
        #pragma unroll
        for (int s = 0; s < DSTATE; s++) {
            h[s] = fmaf(h[s], __expf(dtv * A[s]), dtx * Bv[s]);
            yv = fmaf(h[s], Cv[s], yv);
        }
        float zv = xz[r * (2 * DINNER) + DINNER + e];
        float g = zv / (1.f + __expf(-zv));
        y[r * DINNER + e] = (yv + Dv * xv) * g;
    }
}

// ---------------- launch ----------------------------------------------------
extern "C" void kernel_launch(void* const* d_in, const int* in_sizes, int n_in,
                              void* d_out, int out_size)
{
    const float* x         = (const float*)d_in[0];
    const float* in_proj_w = (const float*)d_in[1];
    const float* conv_w    = (const float*)d_in[2];
    const float* conv_b    = (const float*)d_in[3];
    const float* x_proj_w  = (const float*)d_in[4];
    const float* dt_proj_w = (const float*)d_in[5];
    const float* dt_proj_b = (const float*)d_in[6];
    const float* A_log     = (const float*)d_in[7];
    const float* D_skip    = (const float*)d_in[8];
    const float* out_proj_w= (const float*)d_in[9];
    float* out = (float*)d_out;

    float *u, *xz, *xc, *dbl, *dtb, *yb;
    cudaGetSymbolAddress((void**)&u,   g_u);
    cudaGetSymbolAddress((void**)&xz,  g_xz);
    cudaGetSymbolAddress((void**)&xc,  g_xc);
    cudaGetSymbolAddress((void**)&dbl, g_dbl);
    cudaGetSymbolAddress((void**)&dtb, g_dt);
    cudaGetSymbolAddress((void**)&yb,  g_y);

    // 1) RMSNorm
    rmsnorm_kernel<<<NTOK, 256>>>(x, u);

    // 2) in_proj: [16384,1024] @ [4096,1024]^T -> [16384,4096]
    mma_gemm_kernel<0><<<dim3((2 * DINNER) / 128, NTOK / 128), 256>>>(
        u, DMODEL, in_proj_w, DMODEL, xz, 2 * DINNER,
        2 * DINNER, DMODEL, nullptr, nullptr);

    // 3) causal depthwise conv + SiLU -> xc
    conv_silu_kernel<<<(NTOK * DINNER) / 256, 256>>>(xz, conv_w, conv_b, xc);

    // 4) x_proj: [16384,2048] @ [96,2048]^T -> [16384,96]
    mma_gemm_kernel<0><<<dim3(1, NTOK / 128), 256>>>(
        xc, DINNER, x_proj_w, DINNER, dbl, DBL_W,
        DBL_W, DINNER, nullptr, nullptr);

    // 5) dt_proj + bias + softplus: [16384,64] @ [2048,64]^T -> [16384,2048]
    mma_gemm_kernel<1><<<dim3(DINNER / 128, NTOK / 128), 256>>>(
        dbl, DBL_W, dt_proj_w, DTRANK, dtb, DINNER,
        DINNER, DTRANK, dt_proj_b, nullptr);

    // 6) selective scan + D skip + SiLU(z) gating -> y
    scan_kernel<<<(BATCH * DINNER) / 32, 32>>>(dtb, xc, dbl, xz, A_log, D_skip, yb);

    // 7) out_proj + residual: [16384,2048] @ [1024,2048]^T + x -> out
    mma_gemm_kernel<2><<<dim3(DMODEL / 128, NTOK / 128), 256>>>(
        yb, DINNER, out_proj_w, DINNER, out, DMODEL,
        DMODEL, DINNER, nullptr, x);
}

// round 10
// speedup vs baseline: 2.4173x; 1.4655x over previous
#include <cuda_runtime.h>
#include <math.h>
#include <stdint.h>

#define BATCH   4
#define SEQ     4096
#define DMODEL  1024
#define DINNER  2048
#define DSTATE  16
#define DTRANK  64
#define NTOK    (BATCH * SEQ)          // 16384
#define DBL_W   (DTRANK + 2 * DSTATE)  // 96

// ---------------- scratch (static device globals: allocation-free) ----------
__device__ float g_u  [(size_t)NTOK * DMODEL];
__device__ float g_xz [(size_t)NTOK * 2 * DINNER];
__device__ float g_xc [(size_t)NTOK * DINNER];
__device__ float g_dbl[(size_t)NTOK * DBL_W];
__device__ float g_dt [(size_t)NTOK * DINNER];
__device__ float g_y  [(size_t)NTOK * DINNER];
// tf32-rounded weight copies
__device__ float g_w_in [(size_t)(2 * DINNER) * DMODEL];
__device__ float g_w_x  [(size_t)DBL_W * DINNER];
__device__ float g_w_dt [(size_t)DINNER * DTRANK];
__device__ float g_w_out[(size_t)DMODEL * DINNER];

// ---------------- helpers ----------------------------------------------------
__device__ __forceinline__ float cvt_tf32f(float f) {
    uint32_t o;
    asm("cvt.rn.tf32.f32 %0, %1;" : "=r"(o) : "f"(f));
    return __uint_as_float(o);
}
__device__ __forceinline__ uint32_t cvta_smem_u32(const void* p) {
    uint32_t a;
    asm("{ .reg .u64 t; cvta.to.shared.u64 t, %1; cvt.u32.u64 %0, t; }"
        : "=r"(a) : "l"(p));
    return a;
}
__device__ __forceinline__ void cp16(uint32_t sdst, const void* gsrc, bool valid) {
    int sz = valid ? 16 : 0;
    asm volatile("cp.async.cg.shared.global [%0], [%1], 16, %2;"
                 :: "r"(sdst), "l"(gsrc), "r"(sz) : "memory");
}
#define CP_COMMIT() asm volatile("cp.async.commit_group;" ::: "memory")
#define CP_WAIT(n)  asm volatile("cp.async.wait_group %0;" :: "n"(n) : "memory")

__device__ __forceinline__ void mma_tf32(float* d, const uint32_t* a,
                                         const uint32_t* b) {
    asm volatile(
        "mma.sync.aligned.m16n8k8.row.col.f32.tf32.tf32.f32 "
        "{%0,%1,%2,%3}, {%4,%5,%6,%7}, {%8,%9}, {%0,%1,%2,%3};"
        : "+f"(d[0]), "+f"(d[1]), "+f"(d[2]), "+f"(d[3])
        : "r"(a[0]), "r"(a[1]), "r"(a[2]), "r"(a[3]), "r"(b[0]), "r"(b[1]));
}

// ---------------- weight tf32-round pre-pass ---------------------------------
__global__ __launch_bounds__(256) void cvt4_kernel(
    const float4* __restrict__ in, float4* __restrict__ out, int n4)
{
    int i = blockIdx.x * 256 + threadIdx.x;
    if (i < n4) {
        float4 v = in[i];
        v.x = cvt_tf32f(v.x); v.y = cvt_tf32f(v.y);
        v.z = cvt_tf32f(v.z); v.w = cvt_tf32f(v.w);
        out[i] = v;
    }
}

// =================== tf32 mma.sync GEMM: C = A[M,K] @ W[N,K]^T ==============
// 128x128 CTA tile, BK=16, 256 threads (8 warps 2x4), warp tile 64x32.
// 3-stage cp.async pipeline, 1 sync per chunk, 2 CTAs/SM.
// Operands must be pre-rounded to tf32 (RN) by their producers.
// EPI: 0 none, 1 softplus(acc+bias[n]), 2 acc+resid.  CVT: round output to tf32.

#define SSTRIDE 20              // words per 16-float k-row (conflict-free frags)
#define AS_W    (128 * SSTRIDE) // 2560 words
#define STAGE_W (2 * AS_W)      // 5120 words = 20480 B
#define GEMM_SMEM_BYTES (3 * STAGE_W * 4)   // 61440

template <int EPI, int CVT>
__global__ __launch_bounds__(256, 2) void mma_gemm_kernel(
    const float* __restrict__ A, int lda,
    const float* __restrict__ W, int ldb,
    float* __restrict__ C, int ldc,
    int N, int K,
    const float* __restrict__ bias,
    const float* __restrict__ resid)
{
    extern __shared__ uint32_t sm[];
    uint32_t smb = cvta_smem_u32(sm);

    int tid = threadIdx.x;
    int lane = tid & 31;
    int q = lane >> 2, c = lane & 3;
    int wid = tid >> 5;
    int wm = wid >> 2, wn = wid & 3;
    int brow = blockIdx.y * 128, bcol = blockIdx.x * 128;

    int r0 = tid >> 2, r1 = r0 + 64;
    int kq = (tid & 3) * 4;
    bool bv0 = (bcol + r0) < N, bv1 = (bcol + r1) < N;
    const char* ga0 = (const char*)&A[(size_t)(brow + r0) * lda + kq];
    const char* ga1 = (const char*)&A[(size_t)(brow + r1) * lda + kq];
    const char* gb0 = (const char*)&W[(size_t)(bv0 ? bcol + r0 : 0) * ldb + kq];
    const char* gb1 = (const char*)&W[(size_t)(bv1 ? bcol + r1 : 0) * ldb + kq];

    uint32_t sA0 = smb + (uint32_t)(r0 * SSTRIDE + kq) * 4;
    uint32_t sA1 = smb + (uint32_t)(r1 * SSTRIDE + kq) * 4;
    uint32_t sB0 = sA0 + AS_W * 4;
    uint32_t sB1 = sA1 + AS_W * 4;

    int nch = K >> 4;

    // prologue: stages 0,1
    #pragma unroll
    for (int p = 0; p < 2; p++) {
        uint32_t so = (uint32_t)p * (STAGE_W * 4);
        size_t ko = (size_t)(p << 4) * 4;
        cp16(sA0 + so, ga0 + ko, true);
        cp16(sA1 + so, ga1 + ko, true);
        cp16(sB0 + so, gb0 + ko, bv0);
        cp16(sB1 + so, gb1 + ko, bv1);
        CP_COMMIT();
    }

    float acc[4][4][4];
    #pragma unroll
    for (int mt = 0; mt < 4; mt++)
        #pragma unroll
        for (int nt = 0; nt < 4; nt++)
            #pragma unroll
            for (int i = 0; i < 4; i++) acc[mt][nt][i] = 0.f;

    for (int ch = 0; ch < nch; ch++) {
        if (ch == nch - 1) { CP_WAIT(0); } else { CP_WAIT(1); }
        __syncthreads();
        if (ch + 2 < nch) {
            uint32_t so = (uint32_t)((ch + 2) % 3) * (STAGE_W * 4);
            size_t ko = (size_t)((ch + 2) << 4) * 4;
            cp16(sA0 + so, ga0 + ko, true);
            cp16(sA1 + so, ga1 + ko, true);
            cp16(sB0 + so, gb0 + ko, bv0);
            cp16(sB1 + so, gb1 + ko, bv1);
            CP_COMMIT();
        }
        const uint32_t* AsS = sm + (ch % 3) * STAGE_W;
        const uint32_t* BsS = AsS + AS_W;
        #pragma unroll
        for (int ks = 0; ks < 2; ks++) {
            int kb = ks * 8 + c;
            uint32_t af[4][4];
            #pragma unroll
            for (int mt = 0; mt < 4; mt++) {
                int m = wm * 64 + mt * 16 + q;
                af[mt][0] = AsS[m * SSTRIDE + kb];
                af[mt][1] = AsS[(m + 8) * SSTRIDE + kb];
                af[mt][2] = AsS[m * SSTRIDE + kb + 4];
                af[mt][3] = AsS[(m + 8) * SSTRIDE + kb + 4];
            }
            uint32_t bf[4][2];
            #pragma unroll
            for (int nt = 0; nt < 4; nt++) {
                int n = wn * 32 + nt * 8 + q;
                bf[nt][0] = BsS[n * SSTRIDE + kb];
                bf[nt][1] = BsS[n * SSTRIDE + kb + 4];
            }
            #pragma unroll
            for (int mt = 0; mt < 4; mt++)
                #pragma unroll
                for (int nt = 0; nt < 4; nt++)
                    mma_tf32(acc[mt][nt], af[mt], bf[nt]);
        }
    }

    // epilogue: registers -> global as float2 pairs
    #pragma unroll
    for (int mt = 0; mt < 4; mt++) {
        #pragma unroll
        for (int nt = 0; nt < 4; nt++) {
            int gr = brow + wm * 64 + mt * 16 + q;
            int gc = bcol + wn * 32 + nt * 8 + c * 2;
            if (gc < N) {
                #pragma unroll
                for (int half = 0; half < 2; half++) {
                    int row = gr + half * 8;
                    float v0 = acc[mt][nt][half * 2 + 0];
                    float v1 = acc[mt][nt][half * 2 + 1];
                    if (EPI == 1) {
                        v0 += bias[gc];     v1 += bias[gc + 1];
                        v0 = (v0 > 20.f) ? v0 : log1pf(expf(v0));
                        v1 = (v1 > 20.f) ? v1 : log1pf(expf(v1));
                    } else if (EPI == 2) {
                        float2 rz = *reinterpret_cast<const float2*>(
                            &resid[(size_t)row * ldc + gc]);
                        v0 += rz.x; v1 += rz.y;
                    }
                    if (CVT) { v0 = cvt_tf32f(v0); v1 = cvt_tf32f(v1); }
                    float2 o; o.x = v0; o.y = v1;
                    *reinterpret_cast<float2*>(&C[(size_t)row * ldc + gc]) = o;
                }
            }
        }
    }
}

// ---------------- RMSNorm: one block per token, tf32-rounded output ---------
__global__ __launch_bounds__(256) void rmsnorm_kernel(
    const float* __restrict__ x, float* __restrict__ u)
{
    size_t row = blockIdx.x;
    const float4* xr = reinterpret_cast<const float4*>(x + row * DMODEL);
    float4*       ur = reinterpret_cast<float4*>(u + row * DMODEL);
    int tid = threadIdx.x;
    float4 v = xr[tid];
    float ss = v.x * v.x + v.y * v.y + v.z * v.z + v.w * v.w;
    #pragma unroll
    for (int o = 16; o > 0; o >>= 1) ss += __shfl_xor_sync(0xffffffffu, ss, o);
    __shared__ float ws[8];
    if ((tid & 31) == 0) ws[tid >> 5] = ss;
    __syncthreads();
    float tot = 0.f;
    #pragma unroll
    for (int w = 0; w < 8; w++) tot += ws[w];
    float sc = rsqrtf(tot * (1.f / DMODEL) + 1e-6f);
    ur[tid] = make_float4(cvt_tf32f(v.x * sc), cvt_tf32f(v.y * sc),
                          cvt_tf32f(v.z * sc), cvt_tf32f(v.w * sc));
}

// ---------------- causal depthwise conv (width 4) + SiLU, tf32 output -------
__global__ __launch_bounds__(256) void conv_silu_kernel(
    const float* __restrict__ xz,
    const float* __restrict__ cw,
    const float* __restrict__ cb,
    float* __restrict__ xc)
{
    int idx = blockIdx.x * blockDim.x + threadIdx.x;
    int e = idx & (DINNER - 1);
    int r = idx >> 11;
    int t = r & (SEQ - 1);
    float4 w = *reinterpret_cast<const float4*>(cw + (size_t)e * 4);
    float wv[4] = {w.x, w.y, w.z, w.w};
    float acc = cb[e];
    #pragma unroll
    for (int k = 0; k < 4; k++) {
        int tt = t - 3 + k;
        if (tt >= 0)
            acc = fmaf(wv[k], xz[(size_t)(r - 3 + k) * (2 * DINNER) + e], acc);
    }
    xc[idx] = cvt_tf32f(acc / (1.f + __expf(-acc)));
}

// ---------------- selective scan: 4 threads per channel ---------------------
__global__ __launch_bounds__(128) void scan_kernel(
    const float* __restrict__ dt,
    const float* __restrict__ xc,
    const float* __restrict__ dbl,
    const float* __restrict__ xz,
    const float* __restrict__ A_log,
    const float* __restrict__ D_skip,
    float* __restrict__ y)
{
    int idx = blockIdx.x * 128 + threadIdx.x;     // 0..32767
    int ch = idx >> 2, sub = idx & 3;
    int b = ch >> 11, e = ch & (DINNER - 1);

    float A0, A1, A2, A3;
    {
        const float* ap = A_log + (size_t)e * DSTATE + sub * 4;
        A0 = -expf(ap[0]); A1 = -expf(ap[1]);
        A2 = -expf(ap[2]); A3 = -expf(ap[3]);
    }
    float h0 = 0.f, h1 = 0.f, h2 = 0.f, h3 = 0.f;
    float Dv = D_skip[e];
    size_t base = (size_t)b * SEQ;

    const float* pdt = dt  + base * DINNER + e;
    const float* pxc = xc  + base * DINNER + e;
    const float* pz  = xz  + base * (2 * DINNER) + DINNER + e;
    const float* pbc = dbl + base * DBL_W + DTRANK + sub * 4;
    float*       py  = y   + base * DINNER + e;

    for (int t = 0; t < SEQ; t++) {
        float dtv = *pdt;
        float xv  = *pxc;
        float4 Bv = *reinterpret_cast<const float4*>(pbc);
        float4 Cv = *reinterpret_cast<const float4*>(pbc + DSTATE);
        float dtx = dtv * xv;
        h0 = fmaf(h0, __expf(dtv * A0), dtx * Bv.x);
        h1 = fmaf(h1, __expf(dtv * A1), dtx * Bv.y);
        h2 = fmaf(h2, __expf(dtv * A2), dtx * Bv.z);
        h3 = fmaf(h3, __expf(dtv * A3), dtx * Bv.w);
        float yv = h0 * Cv.x;
        yv = fmaf(h1, Cv.y, yv);
        yv = fmaf(h2, Cv.z, yv);
        yv = fmaf(h3, Cv.w, yv);
        yv += __shfl_xor_sync(0xffffffffu, yv, 1);
        yv += __shfl_xor_sync(0xffffffffu, yv, 2);
        if (sub == 0) {
            float zv = *pz;
            float g = __fdividef(zv, 1.f + __expf(-zv));
            *py = cvt_tf32f((yv + Dv * xv) * g);
        }
        pdt += DINNER; pxc += DINNER; pz += 2 * DINNER;
        pbc += DBL_W;  py += DINNER;
    }
}

// ---------------- launch ----------------------------------------------------
extern "C" void kernel_launch(void* const* d_in, const int* in_sizes, int n_in,
                              void* d_out, int out_size)
{
    const float* x         = (const float*)d_in[0];
    const float* in_proj_w = (const float*)d_in[1];
    const float* conv_w    = (const float*)d_in[2];
    const float* conv_b    = (const float*)d_in[3];
    const float* x_proj_w  = (const float*)d_in[4];
    const float* dt_proj_w = (const float*)d_in[5];
    const float* dt_proj_b = (const float*)d_in[6];
    const float* A_log     = (const float*)d_in[7];
    const float* D_skip    = (const float*)d_in[8];
    const float* out_proj_w= (const float*)d_in[9];
    float* out = (float*)d_out;

    float *u, *xz, *xc, *dbl, *dtb, *yb, *w_in, *w_x, *w_dt, *w_out;
    cudaGetSymbolAddress((void**)&u,    g_u);
    cudaGetSymbolAddress((void**)&xz,   g_xz);
    cudaGetSymbolAddress((void**)&xc,   g_xc);
    cudaGetSymbolAddress((void**)&dbl,  g_dbl);
    cudaGetSymbolAddress((void**)&dtb,  g_dt);
    cudaGetSymbolAddress((void**)&yb,   g_y);
    cudaGetSymbolAddress((void**)&w_in, g_w_in);
    cudaGetSymbolAddress((void**)&w_x,  g_w_x);
    cudaGetSymbolAddress((void**)&w_dt, g_w_dt);
    cudaGetSymbolAddress((void**)&w_out,g_w_out);

    cudaFuncSetAttribute(mma_gemm_kernel<0,0>,
        cudaFuncAttributeMaxDynamicSharedMemorySize, GEMM_SMEM_BYTES);
    cudaFuncSetAttribute(mma_gemm_kernel<0,1>,
        cudaFuncAttributeMaxDynamicSharedMemorySize, GEMM_SMEM_BYTES);
    cudaFuncSetAttribute(mma_gemm_kernel<1,0>,
        cudaFuncAttributeMaxDynamicSharedMemorySize, GEMM_SMEM_BYTES);
    cudaFuncSetAttribute(mma_gemm_kernel<2,0>,
        cudaFuncAttributeMaxDynamicSharedMemorySize, GEMM_SMEM_BYTES);

    // 0) tf32-round all weights once per call (cheap, overlaps nothing)
    {
        int n;
        n = (2 * DINNER) * DMODEL / 4;
        cvt4_kernel<<<(n + 255) / 256, 256>>>((const float4*)in_proj_w, (float4*)w_in, n);
        n = DBL_W * DINNER / 4;
        cvt4_kernel<<<(n + 255) / 256, 256>>>((const float4*)x_proj_w, (float4*)w_x, n);
        n = DINNER * DTRANK / 4;
        cvt4_kernel<<<(n + 255) / 256, 256>>>((const float4*)dt_proj_w, (float4*)w_dt, n);
        n = DMODEL * DINNER / 4;
        cvt4_kernel<<<(n + 255) / 256, 256>>>((const float4*)out_proj_w, (float4*)w_out, n);
    }

    // 1) RMSNorm (tf32-rounded u)
    rmsnorm_kernel<<<NTOK, 256>>>(x, u);

    // 2) in_proj: [16384,1024] @ [4096,1024]^T -> [16384,4096]
    mma_gemm_kernel<0,0><<<dim3((2 * DINNER) / 128, NTOK / 128), 256, GEMM_SMEM_BYTES>>>(
        u, DMODEL, w_in, DMODEL, xz, 2 * DINNER,
        2 * DINNER, DMODEL, nullptr, nullptr);

    // 3) causal depthwise conv + SiLU -> xc (tf32-rounded)
    conv_silu_kernel<<<(NTOK * DINNER) / 256, 256>>>(xz, conv_w, conv_b, xc);

    // 4) x_proj: [16384,2048] @ [96,2048]^T -> [16384,96] (tf32-rounded)
    mma_gemm_kernel<0,1><<<dim3(1, NTOK / 128), 256, GEMM_SMEM_BYTES>>>(
        xc, DINNER, w_x, DINNER, dbl, DBL_W,
        DBL_W, DINNER, nullptr, nullptr);

    // 5) dt_proj + bias + softplus: [16384,64] @ [2048,64]^T -> [16384,2048]
    mma_gemm_kernel<1,0><<<dim3(DINNER / 128, NTOK / 128), 256, GEMM_SMEM_BYTES>>>(
        dbl, DBL_W, w_dt, DTRANK, dtb, DINNER,
        DINNER, DTRANK, dt_proj_b, nullptr);

    // 6) selective scan + D skip + SiLU(z) gating -> y (tf32-rounded)
    scan_kernel<<<(BATCH * DINNER * 4) / 128, 128>>>(dtb, xc, dbl, xz, A_log, D_skip, yb);

    // 7) out_proj + residual: [16384,2048] @ [1024,2048]^T + x -> out
    mma_gemm_kernel<2,0><<<dim3(DMODEL / 128, NTOK / 128), 256, GEMM_SMEM_BYTES>>>(
        yb, DINNER, w_out, DINNER, out, DMODEL,
        DMODEL, DINNER, nullptr, x);
}

// round 11
// speedup vs baseline: 3.1312x; 1.2953x over previous
#include <cuda_runtime.h>
#include <math.h>
#include <stdint.h>

#define BATCH   4
#define SEQ     4096
#define DMODEL  1024
#define DINNER  2048
#define DSTATE  16
#define DTRANK  64
#define NTOK    (BATCH * SEQ)          // 16384
#define DBL_W   (DTRANK + 2 * DSTATE)  // 96

// ---------------- scratch (static device globals: allocation-free) ----------
__device__ float g_u  [(size_t)NTOK * DMODEL];
__device__ float g_xz [(size_t)NTOK * 2 * DINNER];
__device__ float g_xc [(size_t)NTOK * DINNER];
__device__ float g_dbl[(size_t)NTOK * DBL_W];
__device__ float g_dt [(size_t)NTOK * DINNER];
__device__ float g_y  [(size_t)NTOK * DINNER];
// tf32-rounded weight copies
__device__ float g_w_in [(size_t)(2 * DINNER) * DMODEL];
__device__ float g_w_x  [(size_t)DBL_W * DINNER];
__device__ float g_w_dt [(size_t)DINNER * DTRANK];
__device__ float g_w_out[(size_t)DMODEL * DINNER];

// ---------------- helpers ----------------------------------------------------
__device__ __forceinline__ float cvt_tf32f(float f) {
    uint32_t o;
    asm("cvt.rn.tf32.f32 %0, %1;" : "=r"(o) : "f"(f));
    return __uint_as_float(o);
}
__device__ __forceinline__ uint32_t cvta_smem_u32(const void* p) {
    uint32_t a;
    asm("{ .reg .u64 t; cvta.to.shared.u64 t, %1; cvt.u32.u64 %0, t; }"
        : "=r"(a) : "l"(p));
    return a;
}
__device__ __forceinline__ void cp16(uint32_t sdst, const void* gsrc, bool valid) {
    int sz = valid ? 16 : 0;
    asm volatile("cp.async.cg.shared.global [%0], [%1], 16, %2;"
                 :: "r"(sdst), "l"(gsrc), "r"(sz) : "memory");
}
#define CP_COMMIT() asm volatile("cp.async.commit_group;" ::: "memory")
#define CP_WAIT(n)  asm volatile("cp.async.wait_group %0;" :: "n"(n) : "memory")

__device__ __forceinline__ void mma_tf32(float* d, const uint32_t* a,
                                         const uint32_t* b) {
    asm volatile(
        "mma.sync.aligned.m16n8k8.row.col.f32.tf32.tf32.f32 "
        "{%0,%1,%2,%3}, {%4,%5,%6,%7}, {%8,%9}, {%0,%1,%2,%3};"
        : "+f"(d[0]), "+f"(d[1]), "+f"(d[2]), "+f"(d[3])
        : "r"(a[0]), "r"(a[1]), "r"(a[2]), "r"(a[3]), "r"(b[0]), "r"(b[1]));
}

// ---------------- weight tf32-round pre-pass ---------------------------------
__global__ __launch_bounds__(256) void cvt4_kernel(
    const float4* __restrict__ in, float4* __restrict__ out, int n4)
{
    int i = blockIdx.x * 256 + threadIdx.x;
    if (i < n4) {
        float4 v = in[i];
        v.x = cvt_tf32f(v.x); v.y = cvt_tf32f(v.y);
        v.z = cvt_tf32f(v.z); v.w = cvt_tf32f(v.w);
        out[i] = v;
    }
}

// =================== tf32 mma.sync GEMM: C = A[M,K] @ W[N,K]^T ==============
// 128x128 CTA tile, BK=16, 256 threads (8 warps 2x4), warp tile 64x32.
// 4-stage cp.async pipeline, 1 sync per chunk, 2 CTAs/SM.
// Operands must be pre-rounded to tf32 (RN) by their producers.
// EPI: 0 none, 1 softplus(acc+bias[n]), 2 acc+resid.  CVT: round output to tf32.

#define SSTRIDE 20              // words per 16-float k-row (conflict-free frags)
#define AS_W    (128 * SSTRIDE) // 2560 words
#define STAGE_W (2 * AS_W)      // 5120 words = 20480 B
#define NSTAGE  4
#define GEMM_SMEM_BYTES (NSTAGE * STAGE_W * 4)   // 81920

template <int EPI, int CVT>
__global__ __launch_bounds__(256, 2) void mma_gemm_kernel(
    const float* __restrict__ A, int lda,
    const float* __restrict__ W, int ldb,
    float* __restrict__ C, int ldc,
    int N, int K,
    const float* __restrict__ bias,
    const float* __restrict__ resid)
{
    extern __shared__ uint32_t sm[];
    uint32_t smb = cvta_smem_u32(sm);

    int tid = threadIdx.x;
    int lane = tid & 31;
    int q = lane >> 2, c = lane & 3;
    int wid = tid >> 5;
    int wm = wid >> 2, wn = wid & 3;
    int brow = blockIdx.y * 128, bcol = blockIdx.x * 128;

    int r0 = tid >> 2, r1 = r0 + 64;
    int kq = (tid & 3) * 4;
    bool bv0 = (bcol + r0) < N, bv1 = (bcol + r1) < N;
    const char* ga0 = (const char*)&A[(size_t)(brow + r0) * lda + kq];
    const char* ga1 = (const char*)&A[(size_t)(brow + r1) * lda + kq];
    const char* gb0 = (const char*)&W[(size_t)(bv0 ? bcol + r0 : 0) * ldb + kq];
    const char* gb1 = (const char*)&W[(size_t)(bv1 ? bcol + r1 : 0) * ldb + kq];

    uint32_t sA0 = smb + (uint32_t)(r0 * SSTRIDE + kq) * 4;
    uint32_t sA1 = smb + (uint32_t)(r1 * SSTRIDE + kq) * 4;
    uint32_t sB0 = sA0 + AS_W * 4;
    uint32_t sB1 = sA1 + AS_W * 4;

    int nch = K >> 4;            // >= 4 for all our GEMMs

    // prologue: stages 0..2
    #pragma unroll
    for (int p = 0; p < 3; p++) {
        uint32_t so = (uint32_t)p * (STAGE_W * 4);
        size_t ko = (size_t)(p << 4) * 4;
        cp16(sA0 + so, ga0 + ko, true);
        cp16(sA1 + so, ga1 + ko, true);
        cp16(sB0 + so, gb0 + ko, bv0);
        cp16(sB1 + so, gb1 + ko, bv1);
        CP_COMMIT();
    }

    float acc[4][4][4];
    #pragma unroll
    for (int mt = 0; mt < 4; mt++)
        #pragma unroll
        for (int nt = 0; nt < 4; nt++)
            #pragma unroll
            for (int i = 0; i < 4; i++) acc[mt][nt][i] = 0.f;

    for (int ch = 0; ch < nch; ch++) {
        if (ch < nch - 2)       { CP_WAIT(2); }
        else if (ch == nch - 2) { CP_WAIT(1); }
        else                    { CP_WAIT(0); }
        __syncthreads();
        if (ch + 3 < nch) {
            uint32_t so = (uint32_t)((ch + 3) % NSTAGE) * (STAGE_W * 4);
            size_t ko = (size_t)((ch + 3) << 4) * 4;
            cp16(sA0 + so, ga0 + ko, true);
            cp16(sA1 + so, ga1 + ko, true);
            cp16(sB0 + so, gb0 + ko, bv0);
            cp16(sB1 + so, gb1 + ko, bv1);
            CP_COMMIT();
        }
        const uint32_t* AsS = sm + (ch % NSTAGE) * STAGE_W;
        const uint32_t* BsS = AsS + AS_W;
        #pragma unroll
        for (int ks = 0; ks < 2; ks++) {
            int kb = ks * 8 + c;
            uint32_t af[4][4];
            #pragma unroll
            for (int mt = 0; mt < 4; mt++) {
                int m = wm * 64 + mt * 16 + q;
                af[mt][0] = AsS[m * SSTRIDE + kb];
                af[mt][1] = AsS[(m + 8) * SSTRIDE + kb];
                af[mt][2] = AsS[m * SSTRIDE + kb + 4];
                af[mt][3] = AsS[(m + 8) * SSTRIDE + kb + 4];
            }
            uint32_t bf[4][2];
            #pragma unroll
            for (int nt = 0; nt < 4; nt++) {
                int n = wn * 32 + nt * 8 + q;
                bf[nt][0] = BsS[n * SSTRIDE + kb];
                bf[nt][1] = BsS[n * SSTRIDE + kb + 4];
            }
            #pragma unroll
            for (int mt = 0; mt < 4; mt++)
                #pragma unroll
                for (int nt = 0; nt < 4; nt++)
                    mma_tf32(acc[mt][nt], af[mt], bf[nt]);
        }
    }

    // epilogue: registers -> global as float2 pairs
    #pragma unroll
    for (int mt = 0; mt < 4; mt++) {
        #pragma unroll
        for (int nt = 0; nt < 4; nt++) {
            int gr = brow + wm * 64 + mt * 16 + q;
            int gc = bcol + wn * 32 + nt * 8 + c * 2;
            if (gc < N) {
                #pragma unroll
                for (int half = 0; half < 2; half++) {
                    int row = gr + half * 8;
                    float v0 = acc[mt][nt][half * 2 + 0];
                    float v1 = acc[mt][nt][half * 2 + 1];
                    if (EPI == 1) {
                        v0 += bias[gc];     v1 += bias[gc + 1];
                        v0 = (v0 > 20.f) ? v0 : log1pf(expf(v0));
                        v1 = (v1 > 20.f) ? v1 : log1pf(expf(v1));
                    } else if (EPI == 2) {
                        float2 rz = *reinterpret_cast<const float2*>(
                            &resid[(size_t)row * ldc + gc]);
                        v0 += rz.x; v1 += rz.y;
                    }
                    if (CVT) { v0 = cvt_tf32f(v0); v1 = cvt_tf32f(v1); }
                    float2 o; o.x = v0; o.y = v1;
                    *reinterpret_cast<float2*>(&C[(size_t)row * ldc + gc]) = o;
                }
            }
        }
    }
}

// ---------------- RMSNorm: one block per token, tf32-rounded output ---------
__global__ __launch_bounds__(256) void rmsnorm_kernel(
    const float* __restrict__ x, float* __restrict__ u)
{
    size_t row = blockIdx.x;
    const float4* xr = reinterpret_cast<const float4*>(x + row * DMODEL);
    float4*       ur = reinterpret_cast<float4*>(u + row * DMODEL);
    int tid = threadIdx.x;
    float4 v = xr[tid];
    float ss = v.x * v.x + v.y * v.y + v.z * v.z + v.w * v.w;
    #pragma unroll
    for (int o = 16; o > 0; o >>= 1) ss += __shfl_xor_sync(0xffffffffu, ss, o);
    __shared__ float ws[8];
    if ((tid & 31) == 0) ws[tid >> 5] = ss;
    __syncthreads();
    float tot = 0.f;
    #pragma unroll
    for (int w = 0; w < 8; w++) tot += ws[w];
    float sc = rsqrtf(tot * (1.f / DMODEL) + 1e-6f);
    ur[tid] = make_float4(cvt_tf32f(v.x * sc), cvt_tf32f(v.y * sc),
                          cvt_tf32f(v.z * sc), cvt_tf32f(v.w * sc));
}

// ---------------- causal depthwise conv (width 4) + SiLU, float4 ------------
// one thread per 4 consecutive channels
__global__ __launch_bounds__(256) void conv_silu_kernel(
    const float* __restrict__ xz,
    const float* __restrict__ cw,
    const float* __restrict__ cb,
    float* __restrict__ xc)
{
    int idx = blockIdx.x * blockDim.x + threadIdx.x;   // over NTOK*DINNER/4
    int e4 = (idx & (DINNER / 4 - 1)) * 4;
    int r  = idx >> 9;
    int t  = r & (SEQ - 1);

    float4 w0 = *reinterpret_cast<const float4*>(cw + (size_t)(e4 + 0) * 4);
    float4 w1 = *reinterpret_cast<const float4*>(cw + (size_t)(e4 + 1) * 4);
    float4 w2 = *reinterpret_cast<const float4*>(cw + (size_t)(e4 + 2) * 4);
    float4 w3 = *reinterpret_cast<const float4*>(cw + (size_t)(e4 + 3) * 4);
    float4 acc = *reinterpret_cast<const float4*>(cb + e4);

    #pragma unroll
    for (int k = 0; k < 4; k++) {
        int tt = t - 3 + k;
        if (tt >= 0) {
            float4 xv = *reinterpret_cast<const float4*>(
                xz + (size_t)(r - 3 + k) * (2 * DINNER) + e4);
            float wk0 = (&w0.x)[k], wk1 = (&w1.x)[k];
            float wk2 = (&w2.x)[k], wk3 = (&w3.x)[k];
            acc.x = fmaf(wk0, xv.x, acc.x);
            acc.y = fmaf(wk1, xv.y, acc.y);
            acc.z = fmaf(wk2, xv.z, acc.z);
            acc.w = fmaf(wk3, xv.w, acc.w);
        }
    }
    float4 o;
    o.x = cvt_tf32f(acc.x / (1.f + __expf(-acc.x)));
    o.y = cvt_tf32f(acc.y / (1.f + __expf(-acc.y)));
    o.z = cvt_tf32f(acc.z / (1.f + __expf(-acc.z)));
    o.w = cvt_tf32f(acc.w / (1.f + __expf(-acc.w)));
    *reinterpret_cast<float4*>(xc + (size_t)r * DINNER + e4) = o;
}

// ---------------- selective scan: 4 threads/channel, time-unrolled x4 -------
#define TUNROLL 4
__global__ __launch_bounds__(128) void scan_kernel(
    const float* __restrict__ dt,
    const float* __restrict__ xc,
    const float* __restrict__ dbl,
    const float* __restrict__ xz,
    const float* __restrict__ A_log,
    const float* __restrict__ D_skip,
    float* __restrict__ y)
{
    int idx = blockIdx.x * 128 + threadIdx.x;     // 0..32767
    int ch = idx >> 2, sub = idx & 3;
    int b = ch >> 11, e = ch & (DINNER - 1);

    float A0, A1, A2, A3;
    {
        const float* ap = A_log + (size_t)e * DSTATE + sub * 4;
        A0 = -expf(ap[0]); A1 = -expf(ap[1]);
        A2 = -expf(ap[2]); A3 = -expf(ap[3]);
    }
    float h0 = 0.f, h1 = 0.f, h2 = 0.f, h3 = 0.f;
    float Dv = D_skip[e];
    size_t base = (size_t)b * SEQ;

    const float* pdt = dt  + base * DINNER + e;
    const float* pxc = xc  + base * DINNER + e;
    const float* pz  = xz  + base * (2 * DINNER) + DINNER + e;
    const float* pbc = dbl + base * DBL_W + DTRANK + sub * 4;
    float*       py  = y   + base * DINNER + e;

    for (int t = 0; t < SEQ; t += TUNROLL) {
        // hoisted loads: high MLP
        float dtv[TUNROLL], xv[TUNROLL], zv[TUNROLL];
        float4 Bv[TUNROLL], Cv[TUNROLL];
        #pragma unroll
        for (int j = 0; j < TUNROLL; j++) {
            dtv[j] = __ldcs(pdt + (size_t)j * DINNER);
            xv[j]  = __ldcs(pxc + (size_t)j * DINNER);
            Bv[j] = *reinterpret_cast<const float4*>(pbc + (size_t)j * DBL_W);
            Cv[j] = *reinterpret_cast<const float4*>(pbc + (size_t)j * DBL_W + DSTATE);
        }
        if (sub == 0) {
            #pragma unroll
            for (int j = 0; j < TUNROLL; j++)
                zv[j] = __ldcs(pz + (size_t)j * 2 * DINNER);
        }
        #pragma unroll
        for (int j = 0; j < TUNROLL; j++) {
            float dtx = dtv[j] * xv[j];
            h0 = fmaf(h0, __expf(dtv[j] * A0), dtx * Bv[j].x);
            h1 = fmaf(h1, __expf(dtv[j] * A1), dtx * Bv[j].y);
            h2 = fmaf(h2, __expf(dtv[j] * A2), dtx * Bv[j].z);
            h3 = fmaf(h3, __expf(dtv[j] * A3), dtx * Bv[j].w);
            float yv = h0 * Cv[j].x;
            yv = fmaf(h1, Cv[j].y, yv);
            yv = fmaf(h2, Cv[j].z, yv);
            yv = fmaf(h3, Cv[j].w, yv);
            yv += __shfl_xor_sync(0xffffffffu, yv, 1);
            yv += __shfl_xor_sync(0xffffffffu, yv, 2);
            if (sub == 0) {
                float g = __fdividef(zv[j], 1.f + __expf(-zv[j]));
                __stcs(py + (size_t)j * DINNER, cvt_tf32f((yv + Dv * xv[j]) * g));
            }
        }
        pdt += TUNROLL * DINNER; pxc += TUNROLL * DINNER;
        pz  += TUNROLL * 2 * DINNER;
        pbc += TUNROLL * DBL_W;  py += TUNROLL * DINNER;
    }
}

// ---------------- launch ----------------------------------------------------
extern "C" void kernel_launch(void* const* d_in, const int* in_sizes, int n_in,
                              void* d_out, int out_size)
{
    const float* x         = (const float*)d_in[0];
    const float* in_proj_w = (const float*)d_in[1];
    const float* conv_w    = (const float*)d_in[2];
    const float* conv_b    = (const float*)d_in[3];
    const float* x_proj_w  = (const float*)d_in[4];
    const float* dt_proj_w = (const float*)d_in[5];
    const float* dt_proj_b = (const float*)d_in[6];
    const float* A_log     = (const float*)d_in[7];
    const float* D_skip    = (const float*)d_in[8];
    const float* out_proj_w= (const float*)d_in[9];
    float* out = (float*)d_out;

    float *u, *xz, *xc, *dbl, *dtb, *yb, *w_in, *w_x, *w_dt, *w_out;
    cudaGetSymbolAddress((void**)&u,    g_u);
    cudaGetSymbolAddress((void**)&xz,   g_xz);
    cudaGetSymbolAddress((void**)&xc,   g_xc);
    cudaGetSymbolAddress((void**)&dbl,  g_dbl);
    cudaGetSymbolAddress((void**)&dtb,  g_dt);
    cudaGetSymbolAddress((void**)&yb,   g_y);
    cudaGetSymbolAddress((void**)&w_in, g_w_in);
    cudaGetSymbolAddress((void**)&w_x,  g_w_x);
    cudaGetSymbolAddress((void**)&w_dt, g_w_dt);
    cudaGetSymbolAddress((void**)&w_out,g_w_out);

    cudaFuncSetAttribute(mma_gemm_kernel<0,0>,
        cudaFuncAttributeMaxDynamicSharedMemorySize, GEMM_SMEM_BYTES);
    cudaFuncSetAttribute(mma_gemm_kernel<0,1>,
        cudaFuncAttributeMaxDynamicSharedMemorySize, GEMM_SMEM_BYTES);
    cudaFuncSetAttribute(mma_gemm_kernel<1,0>,
        cudaFuncAttributeMaxDynamicSharedMemorySize, GEMM_SMEM_BYTES);
    cudaFuncSetAttribute(mma_gemm_kernel<2,0>,
        cudaFuncAttributeMaxDynamicSharedMemorySize, GEMM_SMEM_BYTES);

    // 0) tf32-round all weights once per call
    {
        int n;
        n = (2 * DINNER) * DMODEL / 4;
        cvt4_kernel<<<(n + 255) / 256, 256>>>((const float4*)in_proj_w, (float4*)w_in, n);
        n = DBL_W * DINNER / 4;
        cvt4_kernel<<<(n + 255) / 256, 256>>>((const float4*)x_proj_w, (float4*)w_x, n);
        n = DINNER * DTRANK / 4;
        cvt4_kernel<<<(n + 255) / 256, 256>>>((const float4*)dt_proj_w, (float4*)w_dt, n);
        n = DMODEL * DINNER / 4;
        cvt4_kernel<<<(n + 255) / 256, 256>>>((const float4*)out_proj_w, (float4*)w_out, n);
    }

    // 1) RMSNorm (tf32-rounded u)
    rmsnorm_kernel<<<NTOK, 256>>>(x, u);

    // 2) in_proj: [16384,1024] @ [4096,1024]^T -> [16384,4096]
    mma_gemm_kernel<0,0><<<dim3((2 * DINNER) / 128, NTOK / 128), 256, GEMM_SMEM_BYTES>>>(
        u, DMODEL, w_in, DMODEL, xz, 2 * DINNER,
        2 * DINNER, DMODEL, nullptr, nullptr);

    // 3) causal depthwise conv + SiLU -> xc (tf32-rounded)
    conv_silu_kernel<<<(NTOK * DINNER / 4) / 256, 256>>>(xz, conv_w, conv_b, xc);

    // 4) x_proj: [16384,2048] @ [96,2048]^T -> [16384,96] (tf32-rounded)
    mma_gemm_kernel<0,1><<<dim3(1, NTOK / 128), 256, GEMM_SMEM_BYTES>>>(
        xc, DINNER, w_x, DINNER, dbl, DBL_W,
        DBL_W, DINNER, nullptr, nullptr);

    // 5) dt_proj + bias + softplus: [16384,64] @ [2048,64]^T -> [16384,2048]
    mma_gemm_kernel<1,0><<<dim3(DINNER / 128, NTOK / 128), 256, GEMM_SMEM_BYTES>>>(
        dbl, DBL_W, w_dt, DTRANK, dtb, DINNER,
        DINNER, DTRANK, dt_proj_b, nullptr);

    // 6) selective scan + D skip + SiLU(z) gating -> y (tf32-rounded)
    scan_kernel<<<(BATCH * DINNER * 4) / 128, 128>>>(dtb, xc, dbl, xz, A_log, D_skip, yb);

    // 7) out_proj + residual: [16384,2048] @ [1024,2048]^T + x -> out
    mma_gemm_kernel<2,0><<<dim3(DMODEL / 128, NTOK / 128), 256, GEMM_SMEM_BYTES>>>(
        yb, DINNER, w_out, DINNER, out, DMODEL,
        DMODEL, DINNER, nullptr, x);
}

// round 12
// speedup vs baseline: 3.6092x; 1.1527x over previous
#include <cuda_runtime.h>
#include <math.h>
#include <stdint.h>

#define BATCH   4
#define SEQ     4096
#define DMODEL  1024
#define DINNER  2048
#define DSTATE  16
#define DTRANK  64
#define NTOK    (BATCH * SEQ)          // 16384
#define DBL_W   (DTRANK + 2 * DSTATE)  // 96

// ---------------- scratch (static device globals: allocation-free) ----------
__device__ float g_u  [(size_t)NTOK * DMODEL];
__device__ float g_xz [(size_t)NTOK * 2 * DINNER];
__device__ float g_xc [(size_t)NTOK * DINNER];
__device__ float g_dbl[(size_t)NTOK * DBL_W];
__device__ float g_dt [(size_t)NTOK * DINNER];
__device__ float g_y  [(size_t)NTOK * DINNER];
// tf32-rounded weight copies (contiguous so one cvt kernel covers all)
#define W_IN_SZ  ((size_t)(2 * DINNER) * DMODEL)
#define W_X_SZ   ((size_t)DBL_W * DINNER)
#define W_DT_SZ  ((size_t)DINNER * DTRANK)
#define W_OUT_SZ ((size_t)DMODEL * DINNER)
__device__ float g_w_in [W_IN_SZ];
__device__ float g_w_x  [W_X_SZ];
__device__ float g_w_dt [W_DT_SZ];
__device__ float g_w_out[W_OUT_SZ];

// ---------------- helpers ----------------------------------------------------
__device__ __forceinline__ float cvt_tf32f(float f) {
    uint32_t o;
    asm("cvt.rn.tf32.f32 %0, %1;" : "=r"(o) : "f"(f));
    return __uint_as_float(o);
}
__device__ __forceinline__ uint32_t cvta_smem_u32(const void* p) {
    uint32_t a;
    asm("{ .reg .u64 t; cvta.to.shared.u64 t, %1; cvt.u32.u64 %0, t; }"
        : "=r"(a) : "l"(p));
    return a;
}
__device__ __forceinline__ void cp16(uint32_t sdst, const void* gsrc, bool valid) {
    int sz = valid ? 16 : 0;
    asm volatile("cp.async.cg.shared.global [%0], [%1], 16, %2;"
                 :: "r"(sdst), "l"(gsrc), "r"(sz) : "memory");
}
#define CP_COMMIT() asm volatile("cp.async.commit_group;" ::: "memory")
#define CP_WAIT(n)  asm volatile("cp.async.wait_group %0;" :: "n"(n) : "memory")

__device__ __forceinline__ void mma_tf32(float* d, const uint32_t* a,
                                         const uint32_t* b) {
    asm volatile(
        "mma.sync.aligned.m16n8k8.row.col.f32.tf32.tf32.f32 "
        "{%0,%1,%2,%3}, {%4,%5,%6,%7}, {%8,%9}, {%0,%1,%2,%3};"
        : "+f"(d[0]), "+f"(d[1]), "+f"(d[2]), "+f"(d[3])
        : "r"(a[0]), "r"(a[1]), "r"(a[2]), "r"(a[3]), "r"(b[0]), "r"(b[1]));
}

// ---------------- weight tf32-round pre-pass (4 weights, 1 kernel) ----------
__global__ __launch_bounds__(256) void cvt_weights_kernel(
    const float4* __restrict__ w_in_s,  float4* __restrict__ w_in_d,
    const float4* __restrict__ w_x_s,   float4* __restrict__ w_x_d,
    const float4* __restrict__ w_dt_s,  float4* __restrict__ w_dt_d,
    const float4* __restrict__ w_out_s, float4* __restrict__ w_out_d)
{
    const int n0 = W_IN_SZ / 4, n1 = n0 + W_X_SZ / 4;
    const int n2 = n1 + W_DT_SZ / 4, n3 = n2 + W_OUT_SZ / 4;
    int i = blockIdx.x * 256 + threadIdx.x;
    const float4* src; float4* dst; int off;
    if      (i < n0) { src = w_in_s;  dst = w_in_d;  off = i; }
    else if (i < n1) { src = w_x_s;   dst = w_x_d;   off = i - n0; }
    else if (i < n2) { src = w_dt_s;  dst = w_dt_d;  off = i - n1; }
    else if (i < n3) { src = w_out_s; dst = w_out_d; off = i - n2; }
    else return;
    float4 v = src[off];
    v.x = cvt_tf32f(v.x); v.y = cvt_tf32f(v.y);
    v.z = cvt_tf32f(v.z); v.w = cvt_tf32f(v.w);
    dst[off] = v;
}

// =================== tf32 mma.sync GEMM: C = A[M,K] @ W[N,K]^T ==============
// CTA tile 128x256, 256 threads (8 warps 2x4), warp tile 64x64
// (4x8 grid of m16n8k8, 128 acc regs). BK=16, 4-stage cp.async, 1 CTA/SM.
// Operands must be pre-rounded to tf32 (RN) by their producers.
// EPI: 0 none, 1 softplus(acc+bias[n]), 2 acc+resid.  CVT: round output.

#define SSTRIDE 20               // words per 16-float k-row (conflict-free frags)
#define AS_W    (128 * SSTRIDE)  // 2560 words
#define BS_W    (256 * SSTRIDE)  // 5120 words
#define STAGE_W (AS_W + BS_W)    // 7680 words = 30720 B
#define NSTAGE  4
#define GEMM_SMEM_BYTES (NSTAGE * STAGE_W * 4)   // 122880

template <int EPI, int CVT>
__global__ __launch_bounds__(256, 1) void mma_gemm_kernel(
    const float* __restrict__ A, int lda,
    const float* __restrict__ W, int ldb,
    float* __restrict__ C, int ldc,
    int N, int K,
    const float* __restrict__ bias,
    const float* __restrict__ resid)
{
    extern __shared__ uint32_t sm[];
    uint32_t smb = cvta_smem_u32(sm);

    int tid = threadIdx.x;
    int lane = tid & 31;
    int q = lane >> 2, c = lane & 3;
    int wid = tid >> 5;
    int wm = wid >> 2, wn = wid & 3;            // 2 x 4 warp grid
    int brow = blockIdx.y * 128, bcol = blockIdx.x * 256;

    // global->smem: A 512 f4 (2/thr), B 1024 f4 (4/thr)
    int rA = tid >> 2;                          // 0..63
    int kq = (tid & 3) * 4;
    const char* gA0 = (const char*)&A[(size_t)(brow + rA) * lda + kq];
    const char* gA1 = (const char*)&A[(size_t)(brow + rA + 64) * lda + kq];
    bool bv0 = (bcol + rA)       < N;
    bool bv1 = (bcol + rA + 64)  < N;
    bool bv2 = (bcol + rA + 128) < N;
    bool bv3 = (bcol + rA + 192) < N;
    const char* gB0 = (const char*)&W[(size_t)(bv0 ? bcol + rA       : 0) * ldb + kq];
    const char* gB1 = (const char*)&W[(size_t)(bv1 ? bcol + rA + 64  : 0) * ldb + kq];
    const char* gB2 = (const char*)&W[(size_t)(bv2 ? bcol + rA + 128 : 0) * ldb + kq];
    const char* gB3 = (const char*)&W[(size_t)(bv3 ? bcol + rA + 192 : 0) * ldb + kq];

    uint32_t sA0 = smb + (uint32_t)(rA * SSTRIDE + kq) * 4;
    uint32_t sA1 = sA0 + 64 * SSTRIDE * 4;
    uint32_t sB0 = smb + (uint32_t)(AS_W + rA * SSTRIDE + kq) * 4;
    uint32_t sB1 = sB0 + 64  * SSTRIDE * 4;
    uint32_t sB2 = sB0 + 128 * SSTRIDE * 4;
    uint32_t sB3 = sB0 + 192 * SSTRIDE * 4;

    int nch = K >> 4;            // >= 4 for all our GEMMs

    #pragma unroll
    for (int p = 0; p < 3; p++) {
        uint32_t so = (uint32_t)p * (STAGE_W * 4);
        size_t ko = (size_t)(p << 4) * 4;
        cp16(sA0 + so, gA0 + ko, true);
        cp16(sA1 + so, gA1 + ko, true);
        cp16(sB0 + so, gB0 + ko, bv0);
        cp16(sB1 + so, gB1 + ko, bv1);
        cp16(sB2 + so, gB2 + ko, bv2);
        cp16(sB3 + so, gB3 + ko, bv3);
        CP_COMMIT();
    }

    float acc[4][8][4];
    #pragma unroll
    for (int mt = 0; mt < 4; mt++)
        #pragma unroll
        for (int nt = 0; nt < 8; nt++)
            #pragma unroll
            for (int i = 0; i < 4; i++) acc[mt][nt][i] = 0.f;

    for (int ch = 0; ch < nch; ch++) {
        if (ch < nch - 2)       { CP_WAIT(2); }
        else if (ch == nch - 2) { CP_WAIT(1); }
        else                    { CP_WAIT(0); }
        __syncthreads();
        if (ch + 3 < nch) {
            uint32_t so = (uint32_t)((ch + 3) % NSTAGE) * (STAGE_W * 4);
            size_t ko = (size_t)((ch + 3) << 4) * 4;
            cp16(sA0 + so, gA0 + ko, true);
            cp16(sA1 + so, gA1 + ko, true);
            cp16(sB0 + so, gB0 + ko, bv0);
            cp16(sB1 + so, gB1 + ko, bv1);
            cp16(sB2 + so, gB2 + ko, bv2);
            cp16(sB3 + so, gB3 + ko, bv3);
            CP_COMMIT();
        }
        const uint32_t* AsS = sm + (ch % NSTAGE) * STAGE_W;
        const uint32_t* BsS = AsS + AS_W;
        #pragma unroll
        for (int ks = 0; ks < 2; ks++) {
            int kb = ks * 8 + c;
            uint32_t af[4][4];
            #pragma unroll
            for (int mt = 0; mt < 4; mt++) {
                int m = wm * 64 + mt * 16 + q;
                af[mt][0] = AsS[m * SSTRIDE + kb];
                af[mt][1] = AsS[(m + 8) * SSTRIDE + kb];
                af[mt][2] = AsS[m * SSTRIDE + kb + 4];
                af[mt][3] = AsS[(m + 8) * SSTRIDE + kb + 4];
            }
            uint32_t bf[8][2];
            #pragma unroll
            for (int nt = 0; nt < 8; nt++) {
                int n = wn * 64 + nt * 8 + q;
                bf[nt][0] = BsS[n * SSTRIDE + kb];
                bf[nt][1] = BsS[n * SSTRIDE + kb + 4];
            }
            #pragma unroll
            for (int mt = 0; mt < 4; mt++)
                #pragma unroll
                for (int nt = 0; nt < 8; nt++)
                    mma_tf32(acc[mt][nt], af[mt], bf[nt]);
        }
    }

    // epilogue: registers -> global as float2 pairs
    #pragma unroll
    for (int mt = 0; mt < 4; mt++) {
        #pragma unroll
        for (int nt = 0; nt < 8; nt++) {
            int gr = brow + wm * 64 + mt * 16 + q;
            int gc = bcol + wn * 64 + nt * 8 + c * 2;
            if (gc < N) {
                #pragma unroll
                for (int half = 0; half < 2; half++) {
                    int row = gr + half * 8;
                    float v0 = acc[mt][nt][half * 2 + 0];
                    float v1 = acc[mt][nt][half * 2 + 1];
                    if (EPI == 1) {
                        v0 += bias[gc];     v1 += bias[gc + 1];
                        v0 = (v0 > 20.f) ? v0 : log1pf(expf(v0));
                        v1 = (v1 > 20.f) ? v1 : log1pf(expf(v1));
                    } else if (EPI == 2) {
                        float2 rz = *reinterpret_cast<const float2*>(
                            &resid[(size_t)row * ldc + gc]);
                        v0 += rz.x; v1 += rz.y;
                    }
                    if (CVT) { v0 = cvt_tf32f(v0); v1 = cvt_tf32f(v1); }
                    float2 o; o.x = v0; o.y = v1;
                    *reinterpret_cast<float2*>(&C[(size_t)row * ldc + gc]) = o;
                }
            }
        }
    }
}

// ---------------- RMSNorm: one block per token, tf32-rounded output ---------
__global__ __launch_bounds__(256) void rmsnorm_kernel(
    const float* __restrict__ x, float* __restrict__ u)
{
    size_t row = blockIdx.x;
    const float4* xr = reinterpret_cast<const float4*>(x + row * DMODEL);
    float4*       ur = reinterpret_cast<float4*>(u + row * DMODEL);
    int tid = threadIdx.x;
    float4 v = xr[tid];
    float ss = v.x * v.x + v.y * v.y + v.z * v.z + v.w * v.w;
    #pragma unroll
    for (int o = 16; o > 0; o >>= 1) ss += __shfl_xor_sync(0xffffffffu, ss, o);
    __shared__ float ws[8];
    if ((tid & 31) == 0) ws[tid >> 5] = ss;
    __syncthreads();
    float tot = 0.f;
    #pragma unroll
    for (int w = 0; w < 8; w++) tot += ws[w];
    float sc = rsqrtf(tot * (1.f / DMODEL) + 1e-6f);
    ur[tid] = make_float4(cvt_tf32f(v.x * sc), cvt_tf32f(v.y * sc),
                          cvt_tf32f(v.z * sc), cvt_tf32f(v.w * sc));
}

// ---------------- causal depthwise conv (width 4) + SiLU, float4 ------------
__global__ __launch_bounds__(256) void conv_silu_kernel(
    const float* __restrict__ xz,
    const float* __restrict__ cw,
    const float* __restrict__ cb,
    float* __restrict__ xc)
{
    int idx = blockIdx.x * blockDim.x + threadIdx.x;   // over NTOK*DINNER/4
    int e4 = (idx & (DINNER / 4 - 1)) * 4;
    int r  = idx >> 9;
    int t  = r & (SEQ - 1);

    float4 w0 = *reinterpret_cast<const float4*>(cw + (size_t)(e4 + 0) * 4);
    float4 w1 = *reinterpret_cast<const float4*>(cw + (size_t)(e4 + 1) * 4);
    float4 w2 = *reinterpret_cast<const float4*>(cw + (size_t)(e4 + 2) * 4);
    float4 w3 = *reinterpret_cast<const float4*>(cw + (size_t)(e4 + 3) * 4);
    float4 acc = *reinterpret_cast<const float4*>(cb + e4);

    #pragma unroll
    for (int k = 0; k < 4; k++) {
        int tt = t - 3 + k;
        if (tt >= 0) {
            float4 xv = *reinterpret_cast<const float4*>(
                xz + (size_t)(r - 3 + k) * (2 * DINNER) + e4);
            float wk0 = (&w0.x)[k], wk1 = (&w1.x)[k];
            float wk2 = (&w2.x)[k], wk3 = (&w3.x)[k];
            acc.x = fmaf(wk0, xv.x, acc.x);
            acc.y = fmaf(wk1, xv.y, acc.y);
            acc.z = fmaf(wk2, xv.z, acc.z);
            acc.w = fmaf(wk3, xv.w, acc.w);
        }
    }
    float4 o;
    o.x = cvt_tf32f(acc.x / (1.f + __expf(-acc.x)));
    o.y = cvt_tf32f(acc.y / (1.f + __expf(-acc.y)));
    o.z = cvt_tf32f(acc.z / (1.f + __expf(-acc.z)));
    o.w = cvt_tf32f(acc.w / (1.f + __expf(-acc.w)));
    *reinterpret_cast<float4*>(xc + (size_t)r * DINNER + e4) = o;
}

// ---------------- selective scan: 4 threads/channel, time-unrolled x8 -------
#define TUNROLL 8
__global__ __launch_bounds__(128) void scan_kernel(
    const float* __restrict__ dt,
    const float* __restrict__ xc,
    const float* __restrict__ dbl,
    const float* __restrict__ xz,
    const float* __restrict__ A_log,
    const float* __restrict__ D_skip,
    float* __restrict__ y)
{
    int idx = blockIdx.x * 128 + threadIdx.x;     // 0..32767
    int ch = idx >> 2, sub = idx & 3;
    int b = ch >> 11, e = ch & (DINNER - 1);

    float A0, A1, A2, A3;
    {
        const float* ap = A_log + (size_t)e * DSTATE + sub * 4;
        A0 = -expf(ap[0]); A1 = -expf(ap[1]);
        A2 = -expf(ap[2]); A3 = -expf(ap[3]);
    }
    float h0 = 0.f, h1 = 0.f, h2 = 0.f, h3 = 0.f;
    float Dv = D_skip[e];
    size_t base = (size_t)b * SEQ;

    const float* pdt = dt  + base * DINNER + e;
    const float* pxc = xc  + base * DINNER + e;
    const float* pz  = xz  + base * (2 * DINNER) + DINNER + e;
    const float* pbc = dbl + base * DBL_W + DTRANK + sub * 4;
    float*       py  = y   + base * DINNER + e;

    for (int t = 0; t < SEQ; t += TUNROLL) {
        float dtv[TUNROLL], xv[TUNROLL], zv[TUNROLL];
        float4 Bv[TUNROLL], Cv[TUNROLL];
        #pragma unroll
        for (int j = 0; j < TUNROLL; j++) {
            dtv[j] = __ldcs(pdt + (size_t)j * DINNER);
            xv[j]  = __ldcs(pxc + (size_t)j * DINNER);
            Bv[j] = *reinterpret_cast<const float4*>(pbc + (size_t)j * DBL_W);
            Cv[j] = *reinterpret_cast<const float4*>(pbc + (size_t)j * DBL_W + DSTATE);
        }
        if (sub == 0) {
            #pragma unroll
            for (int j = 0; j < TUNROLL; j++)
                zv[j] = __ldcs(pz + (size_t)j * 2 * DINNER);
        }
        #pragma unroll
        for (int j = 0; j < TUNROLL; j++) {
            float dtx = dtv[j] * xv[j];
            h0 = fmaf(h0, __expf(dtv[j] * A0), dtx * Bv[j].x);
            h1 = fmaf(h1, __expf(dtv[j] * A1), dtx * Bv[j].y);
            h2 = fmaf(h2, __expf(dtv[j] * A2), dtx * Bv[j].z);
            h3 = fmaf(h3, __expf(dtv[j] * A3), dtx * Bv[j].w);
            float yv = h0 * Cv[j].x;
            yv = fmaf(h1, Cv[j].y, yv);
            yv = fmaf(h2, Cv[j].z, yv);
            yv = fmaf(h3, Cv[j].w, yv);
            yv += __shfl_xor_sync(0xffffffffu, yv, 1);
            yv += __shfl_xor_sync(0xffffffffu, yv, 2);
            if (sub == 0) {
                float g = __fdividef(zv[j], 1.f + __expf(-zv[j]));
                __stcs(py + (size_t)j * DINNER, cvt_tf32f((yv + Dv * xv[j]) * g));
            }
        }
        pdt += TUNROLL * DINNER; pxc += TUNROLL * DINNER;
        pz  += TUNROLL * 2 * DINNER;
        pbc += TUNROLL * DBL_W;  py += TUNROLL * DINNER;
    }
}

// ---------------- launch ----------------------------------------------------
extern "C" void kernel_launch(void* const* d_in, const int* in_sizes, int n_in,
                              void* d_out, int out_size)
{
    const float* x         = (const float*)d_in[0];
    const float* in_proj_w = (const float*)d_in[1];
    const float* conv_w    = (const float*)d_in[2];
    const float* conv_b    = (const float*)d_in[3];
    const float* x_proj_w  = (const float*)d_in[4];
    const float* dt_proj_w = (const float*)d_in[5];
    const float* dt_proj_b = (const float*)d_in[6];
    const float* A_log     = (const float*)d_in[7];
    const float* D_skip    = (const float*)d_in[8];
    const float* out_proj_w= (const float*)d_in[9];
    float* out = (float*)d_out;

    float *u, *xz, *xc, *dbl, *dtb, *yb, *w_in, *w_x, *w_dt, *w_out;
    cudaGetSymbolAddress((void**)&u,    g_u);
    cudaGetSymbolAddress((void**)&xz,   g_xz);
    cudaGetSymbolAddress((void**)&xc,   g_xc);
    cudaGetSymbolAddress((void**)&dbl,  g_dbl);
    cudaGetSymbolAddress((void**)&dtb,  g_dt);
    cudaGetSymbolAddress((void**)&yb,   g_y);
    cudaGetSymbolAddress((void**)&w_in, g_w_in);
    cudaGetSymbolAddress((void**)&w_x,  g_w_x);
    cudaGetSymbolAddress((void**)&w_dt, g_w_dt);
    cudaGetSymbolAddress((void**)&w_out,g_w_out);

    cudaFuncSetAttribute(mma_gemm_kernel<0,0>,
        cudaFuncAttributeMaxDynamicSharedMemorySize, GEMM_SMEM_BYTES);
    cudaFuncSetAttribute(mma_gemm_kernel<0,1>,
        cudaFuncAttributeMaxDynamicSharedMemorySize, GEMM_SMEM_BYTES);
    cudaFuncSetAttribute(mma_gemm_kernel<1,0>,
        cudaFuncAttributeMaxDynamicSharedMemorySize, GEMM_SMEM_BYTES);
    cudaFuncSetAttribute(mma_gemm_kernel<2,0>,
        cudaFuncAttributeMaxDynamicSharedMemorySize, GEMM_SMEM_BYTES);

    // 0) tf32-round all weights in one kernel
    {
        int total4 = (int)((W_IN_SZ + W_X_SZ + W_DT_SZ + W_OUT_SZ) / 4);
        cvt_weights_kernel<<<(total4 + 255) / 256, 256>>>(
            (const float4*)in_proj_w, (float4*)w_in,
            (const float4*)x_proj_w,  (float4*)w_x,
            (const float4*)dt_proj_w, (float4*)w_dt,
            (const float4*)out_proj_w,(float4*)w_out);
    }

    // 1) RMSNorm (tf32-rounded u)
    rmsnorm_kernel<<<NTOK, 256>>>(x, u);

    // 2) in_proj: [16384,1024] @ [4096,1024]^T -> [16384,4096]
    mma_gemm_kernel<0,0><<<dim3((2 * DINNER) / 256, NTOK / 128), 256, GEMM_SMEM_BYTES>>>(
        u, DMODEL, w_in, DMODEL, xz, 2 * DINNER,
        2 * DINNER, DMODEL, nullptr, nullptr);

    // 3) causal depthwise conv + SiLU -> xc (tf32-rounded)
    conv_silu_kernel<<<(NTOK * DINNER / 4) / 256, 256>>>(xz, conv_w, conv_b, xc);

    // 4) x_proj: [16384,2048] @ [96,2048]^T -> [16384,96] (tf32-rounded)
    mma_gemm_kernel<0,1><<<dim3(1, NTOK / 128), 256, GEMM_SMEM_BYTES>>>(
        xc, DINNER, w_x, DINNER, dbl, DBL_W,
        DBL_W, DINNER, nullptr, nullptr);

    // 5) dt_proj + bias + softplus: [16384,64] @ [2048,64]^T -> [16384,2048]
    mma_gemm_kernel<1,0><<<dim3(DINNER / 256, NTOK / 128), 256, GEMM_SMEM_BYTES>>>(
        dbl, DBL_W, w_dt, DTRANK, dtb, DINNER,
        DINNER, DTRANK, dt_proj_b, nullptr);

    // 6) selective scan + D skip + SiLU(z) gating -> y (tf32-rounded)
    scan_kernel<<<(BATCH * DINNER * 4) / 128, 128>>>(dtb, xc, dbl, xz, A_log, D_skip, yb);

    // 7) out_proj + residual: [16384,2048] @ [1024,2048]^T + x -> out
    mma_gemm_kernel<2,0><<<dim3(DMODEL / 256, NTOK / 128), 256, GEMM_SMEM_BYTES>>>(
        yb, DINNER, w_out, DINNER, out, DMODEL,
        DMODEL, DINNER, nullptr, x);
}

// round 13
// speedup vs baseline: 5.1302x; 1.4214x over previous
#include <cuda_runtime.h>
#include <cuda_bf16.h>
#include <math.h>
#include <stdint.h>

#define BATCH   4
#define SEQ     4096
#define DMODEL  1024
#define DINNER  2048
#define DSTATE  16
#define DTRANK  64
#define NTOK    (BATCH * SEQ)          // 16384
#define DBL_W   (DTRANK + 2 * DSTATE)  // 96

typedef __nv_bfloat16 bf16;
typedef __nv_bfloat162 bf162;

// ---------------- scratch (static device globals: allocation-free) ----------
__device__ float g_xz [(size_t)NTOK * 2 * DINNER];   // fp32: conv input + z gate
__device__ float g_dt [(size_t)NTOK * DINNER];       // fp32: exp-sensitive
__device__ bf16  g_u  [(size_t)NTOK * DMODEL];       // MMA operands: bf16
__device__ bf16  g_xc [(size_t)NTOK * DINNER];
__device__ bf16  g_dbl[(size_t)NTOK * DBL_W];
__device__ bf16  g_y  [(size_t)NTOK * DINNER];
#define W_IN_SZ  ((size_t)(2 * DINNER) * DMODEL)
#define W_X_SZ   ((size_t)DBL_W * DINNER)
#define W_DT_SZ  ((size_t)DINNER * DTRANK)
#define W_OUT_SZ ((size_t)DMODEL * DINNER)
__device__ bf16 g_w_in [W_IN_SZ];
__device__ bf16 g_w_x  [W_X_SZ];
__device__ bf16 g_w_dt [W_DT_SZ];
__device__ bf16 g_w_out[W_OUT_SZ];

// ---------------- helpers ----------------------------------------------------
__device__ __forceinline__ uint32_t cvta_smem_u32(const void* p) {
    uint32_t a;
    asm("{ .reg .u64 t; cvta.to.shared.u64 t, %1; cvt.u32.u64 %0, t; }"
        : "=r"(a) : "l"(p));
    return a;
}
__device__ __forceinline__ void cp16(uint32_t sdst, const void* gsrc, bool valid) {
    int sz = valid ? 16 : 0;
    asm volatile("cp.async.cg.shared.global [%0], [%1], 16, %2;"
                 :: "r"(sdst), "l"(gsrc), "r"(sz) : "memory");
}
#define CP_COMMIT() asm volatile("cp.async.commit_group;" ::: "memory")
#define CP_WAIT(n)  asm volatile("cp.async.wait_group %0;" :: "n"(n) : "memory")

__device__ __forceinline__ void mma_bf16(float* d, const uint32_t* a,
                                         const uint32_t* b) {
    asm volatile(
        "mma.sync.aligned.m16n8k16.row.col.f32.bf16.bf16.f32 "
        "{%0,%1,%2,%3}, {%4,%5,%6,%7}, {%8,%9}, {%0,%1,%2,%3};"
        : "+f"(d[0]), "+f"(d[1]), "+f"(d[2]), "+f"(d[3])
        : "r"(a[0]), "r"(a[1]), "r"(a[2]), "r"(a[3]), "r"(b[0]), "r"(b[1]));
}

__device__ __forceinline__ void store_pair(float* C, size_t off, float v0, float v1) {
    float2 o; o.x = v0; o.y = v1;
    *reinterpret_cast<float2*>(C + off) = o;
}
__device__ __forceinline__ void store_pair(bf16* C, size_t off, float v0, float v1) {
    *reinterpret_cast<bf162*>(C + off) = __floats2bfloat162_rn(v0, v1);
}

// ---------------- weight f32 -> bf16 pre-pass (all 4, 1 kernel) -------------
__global__ __launch_bounds__(256) void cvt_weights_kernel(
    const float4* __restrict__ w_in_s,  bf16* __restrict__ w_in_d,
    const float4* __restrict__ w_x_s,   bf16* __restrict__ w_x_d,
    const float4* __restrict__ w_dt_s,  bf16* __restrict__ w_dt_d,
    const float4* __restrict__ w_out_s, bf16* __restrict__ w_out_d)
{
    const int n0 = W_IN_SZ / 4, n1 = n0 + W_X_SZ / 4;
    const int n2 = n1 + W_DT_SZ / 4, n3 = n2 + W_OUT_SZ / 4;
    int i = blockIdx.x * 256 + threadIdx.x;
    const float4* src; bf16* dst; int off;
    if      (i < n0) { src = w_in_s;  dst = w_in_d;  off = i; }
    else if (i < n1) { src = w_x_s;   dst = w_x_d;   off = i - n0; }
    else if (i < n2) { src = w_dt_s;  dst = w_dt_d;  off = i - n1; }
    else if (i < n3) { src = w_out_s; dst = w_out_d; off = i - n2; }
    else return;
    float4 v = src[off];
    bf162 lo = __floats2bfloat162_rn(v.x, v.y);
    bf162 hi = __floats2bfloat162_rn(v.z, v.w);
    uint2 o;
    o.x = *reinterpret_cast<uint32_t*>(&lo);
    o.y = *reinterpret_cast<uint32_t*>(&hi);
    *reinterpret_cast<uint2*>(dst + (size_t)off * 4) = o;
}

// ================ bf16 mma.sync GEMM: C = A[M,K] @ W[N,K]^T =================
// CTA 128x256, 256 threads (8 warps 2x4), warp tile 64x64 (4x8 m16n8k16).
// BK=32 bf16 per stage (same 30720B stage), 4-stage cp.async, 1 CTA/SM.
// EPI: 0 none, 1 softplus(acc+bias[n]), 2 acc+resid. OutT: float or bf16.

#define SSTRIDE 20               // 4B words per 32-bf16 row (16 data + 4 pad)
#define AS_W    (128 * SSTRIDE)
#define BS_W    (256 * SSTRIDE)
#define STAGE_W (AS_W + BS_W)    // 7680 words = 30720 B
#define NSTAGE  4
#define GEMM_SMEM_BYTES (NSTAGE * STAGE_W * 4)   // 122880

template <int EPI, typename OutT>
__global__ __launch_bounds__(256, 1) void mma_gemm_kernel(
    const bf16* __restrict__ A, int lda,
    const bf16* __restrict__ W, int ldb,
    OutT* __restrict__ C, int ldc,
    int N, int K,
    const float* __restrict__ bias,
    const float* __restrict__ resid)
{
    extern __shared__ uint32_t sm[];
    uint32_t smb = cvta_smem_u32(sm);

    int tid = threadIdx.x;
    int lane = tid & 31;
    int q = lane >> 2, c = lane & 3;
    int wid = tid >> 5;
    int wm = wid >> 2, wn = wid & 3;            // 2 x 4 warp grid
    int brow = blockIdx.y * 128, bcol = blockIdx.x * 256;

    // cp.async mapping: rows tid>>2 (+64k), 16B piece tid&3; row = 64B of bf16
    int rA = tid >> 2;                          // 0..63
    int pq = (tid & 3) * 16;                    // byte piece within row
    const char* gA0 = (const char*)(A + (size_t)(brow + rA) * lda) + pq;
    const char* gA1 = (const char*)(A + (size_t)(brow + rA + 64) * lda) + pq;
    bool bv0 = (bcol + rA)       < N;
    bool bv1 = (bcol + rA + 64)  < N;
    bool bv2 = (bcol + rA + 128) < N;
    bool bv3 = (bcol + rA + 192) < N;
    const char* gB0 = (const char*)(W + (size_t)(bv0 ? bcol + rA       : 0) * ldb) + pq;
    const char* gB1 = (const char*)(W + (size_t)(bv1 ? bcol + rA + 64  : 0) * ldb) + pq;
    const char* gB2 = (const char*)(W + (size_t)(bv2 ? bcol + rA + 128 : 0) * ldb) + pq;
    const char* gB3 = (const char*)(W + (size_t)(bv3 ? bcol + rA + 192 : 0) * ldb) + pq;

    uint32_t sA0 = smb + (uint32_t)(rA * SSTRIDE) * 4 + pq;
    uint32_t sA1 = sA0 + 64 * SSTRIDE * 4;
    uint32_t sB0 = smb + (uint32_t)(AS_W + rA * SSTRIDE) * 4 + pq;
    uint32_t sB1 = sB0 + 64  * SSTRIDE * 4;
    uint32_t sB2 = sB0 + 128 * SSTRIDE * 4;
    uint32_t sB3 = sB0 + 192 * SSTRIDE * 4;

    int nch = K >> 5;                  // BK = 32 bf16 (64 bytes per row)
    int npro = nch < 3 ? nch : 3;

    for (int p = 0; p < npro; p++) {
        uint32_t so = (uint32_t)p * (STAGE_W * 4);
        size_t ko = (size_t)(p << 5) * 2;       // 32 bf16 = 64 bytes
        cp16(sA0 + so, gA0 + ko, true);
        cp16(sA1 + so, gA1 + ko, true);
        cp16(sB0 + so, gB0 + ko, bv0);
        cp16(sB1 + so, gB1 + ko, bv1);
        cp16(sB2 + so, gB2 + ko, bv2);
        cp16(sB3 + so, gB3 + ko, bv3);
        CP_COMMIT();
    }

    float acc[4][8][4];
    #pragma unroll
    for (int mt = 0; mt < 4; mt++)
        #pragma unroll
        for (int nt = 0; nt < 8; nt++)
            #pragma unroll
            for (int i = 0; i < 4; i++) acc[mt][nt][i] = 0.f;

    for (int ch = 0; ch < nch; ch++) {
        if (ch < nch - 2)       { CP_WAIT(2); }
        else if (ch == nch - 2) { CP_WAIT(1); }
        else                    { CP_WAIT(0); }
        __syncthreads();
        if (ch + 3 < nch) {
            uint32_t so = (uint32_t)((ch + 3) % NSTAGE) * (STAGE_W * 4);
            size_t ko = (size_t)((ch + 3) << 5) * 2;
            cp16(sA0 + so, gA0 + ko, true);
            cp16(sA1 + so, gA1 + ko, true);
            cp16(sB0 + so, gB0 + ko, bv0);
            cp16(sB1 + so, gB1 + ko, bv1);
            cp16(sB2 + so, gB2 + ko, bv2);
            cp16(sB3 + so, gB3 + ko, bv3);
            CP_COMMIT();
        }
        const uint32_t* AsS = sm + (ch % NSTAGE) * STAGE_W;
        const uint32_t* BsS = AsS + AS_W;
        #pragma unroll
        for (int ks = 0; ks < 2; ks++) {        // two k16 halves of BK=32
            int kb = ks * 8 + c;
            uint32_t af[4][4];
            #pragma unroll
            for (int mt = 0; mt < 4; mt++) {
                int m = wm * 64 + mt * 16 + q;
                af[mt][0] = AsS[m * SSTRIDE + kb];
                af[mt][1] = AsS[(m + 8) * SSTRIDE + kb];
                af[mt][2] = AsS[m * SSTRIDE + kb + 4];
                af[mt][3] = AsS[(m + 8) * SSTRIDE + kb + 4];
            }
            uint32_t bf[8][2];
            #pragma unroll
            for (int nt = 0; nt < 8; nt++) {
                int n = wn * 64 + nt * 8 + q;
                bf[nt][0] = BsS[n * SSTRIDE + kb];
                bf[nt][1] = BsS[n * SSTRIDE + kb + 4];
            }
            #pragma unroll
            for (int mt = 0; mt < 4; mt++)
                #pragma unroll
                for (int nt = 0; nt < 8; nt++)
                    mma_bf16(acc[mt][nt], af[mt], bf[nt]);
        }
    }

    // epilogue: registers -> global as pairs
    #pragma unroll
    for (int mt = 0; mt < 4; mt++) {
        #pragma unroll
        for (int nt = 0; nt < 8; nt++) {
            int gr = brow + wm * 64 + mt * 16 + q;
            int gc = bcol + wn * 64 + nt * 8 + c * 2;
            if (gc < N) {
                #pragma unroll
                for (int half = 0; half < 2; half++) {
                    int row = gr + half * 8;
                    float v0 = acc[mt][nt][half * 2 + 0];
                    float v1 = acc[mt][nt][half * 2 + 1];
                    if (EPI == 1) {
                        v0 += bias[gc];     v1 += bias[gc + 1];
                        v0 = (v0 > 20.f) ? v0 : log1pf(expf(v0));
                        v1 = (v1 > 20.f) ? v1 : log1pf(expf(v1));
                    } else if (EPI == 2) {
                        float2 rz = *reinterpret_cast<const float2*>(
                            &resid[(size_t)row * ldc + gc]);
                        v0 += rz.x; v1 += rz.y;
                    }
                    store_pair(C, (size_t)row * ldc + gc, v0, v1);
                }
            }
        }
    }
}

// ---------------- RMSNorm: one block per token, bf16 output -----------------
__global__ __launch_bounds__(256) void rmsnorm_kernel(
    const float* __restrict__ x, bf16* __restrict__ u)
{
    size_t row = blockIdx.x;
    const float4* xr = reinterpret_cast<const float4*>(x + row * DMODEL);
    int tid = threadIdx.x;
    float4 v = xr[tid];
    float ss = v.x * v.x + v.y * v.y + v.z * v.z + v.w * v.w;
    #pragma unroll
    for (int o = 16; o > 0; o >>= 1) ss += __shfl_xor_sync(0xffffffffu, ss, o);
    __shared__ float ws[8];
    if ((tid & 31) == 0) ws[tid >> 5] = ss;
    __syncthreads();
    float tot = 0.f;
    #pragma unroll
    for (int w = 0; w < 8; w++) tot += ws[w];
    float sc = rsqrtf(tot * (1.f / DMODEL) + 1e-6f);
    bf162 lo = __floats2bfloat162_rn(v.x * sc, v.y * sc);
    bf162 hi = __floats2bfloat162_rn(v.z * sc, v.w * sc);
    uint2 o;
    o.x = *reinterpret_cast<uint32_t*>(&lo);
    o.y = *reinterpret_cast<uint32_t*>(&hi);
    *reinterpret_cast<uint2*>(u + row * DMODEL + (size_t)tid * 4) = o;
}

// ------- causal depthwise conv (width 4) + SiLU: 4 ch x 4 tokens/thread -----
__global__ __launch_bounds__(256) void conv_silu_kernel(
    const float* __restrict__ xz,      // [NTOK, 4096] fp32, xc = cols [0,2048)
    const float* __restrict__ cw,      // [2048, 4]
    const float* __restrict__ cb,
    bf16* __restrict__ xc)             // [NTOK, 2048] bf16
{
    int idx = blockIdx.x * 256 + threadIdx.x;   // NTOK/4 * DINNER/4 jobs
    int e4 = (idx & (DINNER / 4 - 1)) * 4;
    int rg = idx >> 9;
    int r0 = rg * 4;
    int t0 = r0 & (SEQ - 1);

    float4 w0 = *reinterpret_cast<const float4*>(cw + (size_t)(e4 + 0) * 4);
    float4 w1 = *reinterpret_cast<const float4*>(cw + (size_t)(e4 + 1) * 4);
    float4 w2 = *reinterpret_cast<const float4*>(cw + (size_t)(e4 + 2) * 4);
    float4 w3 = *reinterpret_cast<const float4*>(cw + (size_t)(e4 + 3) * 4);
    float4 bias = *reinterpret_cast<const float4*>(cb + e4);

    float4 xv[7];
    #pragma unroll
    for (int j = 0; j < 7; j++) {
        int dt_ = j - 3;
        if (t0 + dt_ >= 0)
            xv[j] = *reinterpret_cast<const float4*>(
                xz + (size_t)(r0 + dt_) * (2 * DINNER) + e4);
        else
            xv[j] = make_float4(0.f, 0.f, 0.f, 0.f);
    }

    #pragma unroll
    for (int i = 0; i < 4; i++) {
        float4 acc = bias;
        #pragma unroll
        for (int k = 0; k < 4; k++) {
            float4 x4 = xv[i + k];
            acc.x = fmaf((&w0.x)[k], x4.x, acc.x);
            acc.y = fmaf((&w1.x)[k], x4.y, acc.y);
            acc.z = fmaf((&w2.x)[k], x4.z, acc.z);
            acc.w = fmaf((&w3.x)[k], x4.w, acc.w);
        }
        float4 s;
        s.x = acc.x / (1.f + __expf(-acc.x));
        s.y = acc.y / (1.f + __expf(-acc.y));
        s.z = acc.z / (1.f + __expf(-acc.z));
        s.w = acc.w / (1.f + __expf(-acc.w));
        bf162 lo = __floats2bfloat162_rn(s.x, s.y);
        bf162 hi = __floats2bfloat162_rn(s.z, s.w);
        uint2 o;
        o.x = *reinterpret_cast<uint32_t*>(&lo);
        o.y = *reinterpret_cast<uint32_t*>(&hi);
        *reinterpret_cast<uint2*>(xc + (size_t)(r0 + i) * DINNER + e4) = o;
    }
}

// ---------------- selective scan: 4 threads/channel, time-unrolled x8 -------
#define TUNROLL 8
__global__ __launch_bounds__(128) void scan_kernel(
    const float* __restrict__ dt,      // fp32
    const bf16*  __restrict__ xc,      // bf16
    const bf16*  __restrict__ dbl,     // bf16 [NTOK,96]
    const float* __restrict__ xz,      // fp32 (z = cols [2048,4096))
    const float* __restrict__ A_log,
    const float* __restrict__ D_skip,
    bf16* __restrict__ y)              // bf16
{
    int idx = blockIdx.x * 128 + threadIdx.x;     // 0..32767
    int ch = idx >> 2, sub = idx & 3;
    int b = ch >> 11, e = ch & (DINNER - 1);

    float A0, A1, A2, A3;
    {
        const float* ap = A_log + (size_t)e * DSTATE + sub * 4;
        A0 = -expf(ap[0]); A1 = -expf(ap[1]);
        A2 = -expf(ap[2]); A3 = -expf(ap[3]);
    }
    float h0 = 0.f, h1 = 0.f, h2 = 0.f, h3 = 0.f;
    float Dv = D_skip[e];
    size_t base = (size_t)b * SEQ;

    const float* pdt = dt  + base * DINNER + e;
    const bf16*  pxc = xc  + base * DINNER + e;
    const float* pz  = xz  + base * (2 * DINNER) + DINNER + e;
    const bf16*  pbc = dbl + base * DBL_W + DTRANK + sub * 4;
    bf16*        py  = y   + base * DINNER + e;

    for (int t = 0; t < SEQ; t += TUNROLL) {
        float dtv[TUNROLL], xv[TUNROLL], zv[TUNROLL];
        float2 B01[TUNROLL], B23[TUNROLL], C01[TUNROLL], C23[TUNROLL];
        #pragma unroll
        for (int j = 0; j < TUNROLL; j++) {
            dtv[j] = __ldcs(pdt + (size_t)j * DINNER);
            xv[j]  = __bfloat162float(pxc[(size_t)j * DINNER]);
            const bf162* pb = reinterpret_cast<const bf162*>(pbc + (size_t)j * DBL_W);
            B01[j] = __bfloat1622float2(pb[0]);
            B23[j] = __bfloat1622float2(pb[1]);
            const bf162* pc = reinterpret_cast<const bf162*>(
                pbc + (size_t)j * DBL_W + DSTATE);
            C01[j] = __bfloat1622float2(pc[0]);
            C23[j] = __bfloat1622float2(pc[1]);
        }
        if (sub == 0) {
            #pragma unroll
            for (int j = 0; j < TUNROLL; j++)
                zv[j] = __ldcs(pz + (size_t)j * 2 * DINNER);
        }
        #pragma unroll
        for (int j = 0; j < TUNROLL; j++) {
            float dtx = dtv[j] * xv[j];
            h0 = fmaf(h0, __expf(dtv[j] * A0), dtx * B01[j].x);
            h1 = fmaf(h1, __expf(dtv[j] * A1), dtx * B01[j].y);
            h2 = fmaf(h2, __expf(dtv[j] * A2), dtx * B23[j].x);
            h3 = fmaf(h3, __expf(dtv[j] * A3), dtx * B23[j].y);
            float yv = h0 * C01[j].x;
            yv = fmaf(h1, C01[j].y, yv);
            yv = fmaf(h2, C23[j].x, yv);
            yv = fmaf(h3, C23[j].y, yv);
            yv += __shfl_xor_sync(0xffffffffu, yv, 1);
            yv += __shfl_xor_sync(0xffffffffu, yv, 2);
            if (sub == 0) {
                float g = __fdividef(zv[j], 1.f + __expf(-zv[j]));
                py[(size_t)j * DINNER] = __float2bfloat16((yv + Dv * xv[j]) * g);
            }
        }
        pdt += TUNROLL * DINNER; pxc += TUNROLL * DINNER;
        pz  += TUNROLL * 2 * DINNER;
        pbc += TUNROLL * DBL_W;  py += TUNROLL * DINNER;
    }
}

// ---------------- launch ----------------------------------------------------
extern "C" void kernel_launch(void* const* d_in, const int* in_sizes, int n_in,
                              void* d_out, int out_size)
{
    const float* x         = (const float*)d_in[0];
    const float* in_proj_w = (const float*)d_in[1];
    const float* conv_w    = (const float*)d_in[2];
    const float* conv_b    = (const float*)d_in[3];
    const float* x_proj_w  = (const float*)d_in[4];
    const float* dt_proj_w = (const float*)d_in[5];
    const float* dt_proj_b = (const float*)d_in[6];
    const float* A_log     = (const float*)d_in[7];
    const float* D_skip    = (const float*)d_in[8];
    const float* out_proj_w= (const float*)d_in[9];
    float* out = (float*)d_out;

    float *xz, *dtb;
    bf16 *u, *xc, *dbl, *yb, *w_in, *w_x, *w_dt, *w_out;
    cudaGetSymbolAddress((void**)&xz,   g_xz);
    cudaGetSymbolAddress((void**)&dtb,  g_dt);
    cudaGetSymbolAddress((void**)&u,    g_u);
    cudaGetSymbolAddress((void**)&xc,   g_xc);
    cudaGetSymbolAddress((void**)&dbl,  g_dbl);
    cudaGetSymbolAddress((void**)&yb,   g_y);
    cudaGetSymbolAddress((void**)&w_in, g_w_in);
    cudaGetSymbolAddress((void**)&w_x,  g_w_x);
    cudaGetSymbolAddress((void**)&w_dt, g_w_dt);
    cudaGetSymbolAddress((void**)&w_out,g_w_out);

    cudaFuncSetAttribute((const void*)mma_gemm_kernel<0, float>,
        cudaFuncAttributeMaxDynamicSharedMemorySize, GEMM_SMEM_BYTES);
    cudaFuncSetAttribute((const void*)mma_gemm_kernel<0, bf16>,
        cudaFuncAttributeMaxDynamicSharedMemorySize, GEMM_SMEM_BYTES);
    cudaFuncSetAttribute((const void*)mma_gemm_kernel<1, float>,
        cudaFuncAttributeMaxDynamicSharedMemorySize, GEMM_SMEM_BYTES);
    cudaFuncSetAttribute((const void*)mma_gemm_kernel<2, float>,
        cudaFuncAttributeMaxDynamicSharedMemorySize, GEMM_SMEM_BYTES);

    // 0) weights -> bf16, one kernel
    {
        int total4 = (int)((W_IN_SZ + W_X_SZ + W_DT_SZ + W_OUT_SZ) / 4);
        cvt_weights_kernel<<<(total4 + 255) / 256, 256>>>(
            (const float4*)in_proj_w, w_in,
            (const float4*)x_proj_w,  w_x,
            (const float4*)dt_proj_w, w_dt,
            (const float4*)out_proj_w,w_out);
    }

    // 1) RMSNorm -> u (bf16)
    rmsnorm_kernel<<<NTOK, 256>>>(x, u);

    // 2) in_proj: [16384,1024]bf16 @ [4096,1024]^T -> xz fp32
    mma_gemm_kernel<0, float><<<dim3((2 * DINNER) / 256, NTOK / 128), 256, GEMM_SMEM_BYTES>>>(
        u, DMODEL, w_in, DMODEL, xz, 2 * DINNER,
        2 * DINNER, DMODEL, nullptr, nullptr);

    // 3) causal depthwise conv + SiLU -> xc (bf16)
    conv_silu_kernel<<<(NTOK / 4) * (DINNER / 4) / 256, 256>>>(xz, conv_w, conv_b, xc);

    // 4) x_proj: [16384,2048]bf16 @ [96,2048]^T -> dbl (bf16)
    mma_gemm_kernel<0, bf16><<<dim3(1, NTOK / 128), 256, GEMM_SMEM_BYTES>>>(
        xc, DINNER, w_x, DINNER, dbl, DBL_W,
        DBL_W, DINNER, nullptr, nullptr);

    // 5) dt_proj + bias + softplus: [16384,64]bf16 @ [2048,64]^T -> dt fp32
    mma_gemm_kernel<1, float><<<dim3(DINNER / 256, NTOK / 128), 256, GEMM_SMEM_BYTES>>>(
        dbl, DBL_W, w_dt, DTRANK, dtb, DINNER,
        DINNER, DTRANK, dt_proj_b, nullptr);

    // 6) selective scan + D skip + SiLU(z) gating -> y (bf16)
    scan_kernel<<<(BATCH * DINNER * 4) / 128, 128>>>(dtb, xc, dbl, xz, A_log, D_skip, yb);

    // 7) out_proj + residual: [16384,2048]bf16 @ [1024,2048]^T + x -> out fp32
    mma_gemm_kernel<2, float><<<dim3(DMODEL / 256, NTOK / 128), 256, GEMM_SMEM_BYTES>>>(
        yb, DINNER, w_out, DINNER, out, DMODEL,
        DMODEL, DINNER, nullptr, x);
}